// round 12
// baseline (speedup 1.0000x reference)
#include <cuda_runtime.h>
#include <cuda_bf16.h>
#include <cstdint>
#include <cstddef>

#define NB 64
#define LS 128

__device__ float g_xg[(size_t)LS*3*NB*4096];

__device__ __forceinline__ float sigm(float x){ return 1.0f/(1.0f+__expf(-x)); }
__device__ __forceinline__ void cpa16(void* dst, const float* src){
    asm volatile("cp.async.ca.shared.global [%0], [%1], 16;"
                 :: "r"((uint32_t)__cvta_generic_to_shared(dst)), "l"(src)); }
__device__ __forceinline__ uint32_t smem_u32(const void* p){
    uint32_t a; asm("{ .reg .u64 t; cvta.to.shared.u64 t, %1; cvt.u32.u64 %0, t; }"
                    : "=r"(a) : "l"(p)); return a; }

// split pair (f0,f1) -> hi bf16x2, lo-residual bf16x2
__device__ __forceinline__ uint2 split2(float f0, float f1){
    __nv_bfloat162 h2 = __floats2bfloat162_rn(f0, f1);
    uint32_t u = *(uint32_t*)&h2;
    float b0 = __uint_as_float(u << 16);
    float b1 = __uint_as_float(u & 0xffff0000u);
    __nv_bfloat162 l2 = __floats2bfloat162_rn(f0 - b0, f1 - b1);
    uint2 r; r.x = u; r.y = *(uint32_t*)&l2;
    return r;
}
__device__ __forceinline__ void ldm4(uint32_t* r, uint32_t addr){
    asm volatile("ldmatrix.sync.aligned.m8n8.x4.shared.b16 {%0,%1,%2,%3}, [%4];"
        : "=r"(r[0]),"=r"(r[1]),"=r"(r[2]),"=r"(r[3]) : "r"(addr));
}
__device__ __forceinline__ void ldm4t(uint32_t* r, uint32_t addr){
    asm volatile("ldmatrix.sync.aligned.m8n8.x4.trans.shared.b16 {%0,%1,%2,%3}, [%4];"
        : "=r"(r[0]),"=r"(r[1]),"=r"(r[2]),"=r"(r[3]) : "r"(addr));
}
__device__ __forceinline__ void mma16816(float* d, const uint32_t* a, uint32_t b0, uint32_t b1){
    asm volatile("mma.sync.aligned.m16n8k16.row.col.f32.bf16.bf16.f32 "
        "{%0,%1,%2,%3}, {%4,%5,%6,%7}, {%8,%9}, {%0,%1,%2,%3};"
        : "+f"(d[0]),"+f"(d[1]),"+f"(d[2]),"+f"(d[3])
        : "r"(a[0]),"r"(a[1]),"r"(a[2]),"r"(a[3]), "r"(b0),"r"(b1));
}
// lane address into 16x16 block of row-major bf16 array, row stride 72 elems
__device__ __forceinline__ uint32_t fraddr(uint32_t base, int row0, int col0, int lane){
    int grp = lane >> 3, lr = lane & 7;
    int row = row0 + lr + (grp & 1) * 8;
    int col = col0 + (grp >> 1) * 8;
    return base + (uint32_t)(row * 72 + col) * 2u;
}
// cluster-scope mbarrier wait (acquire.cluster)
__device__ __forceinline__ void mbar_waitc(uint32_t mbar, uint32_t parity){
    uint32_t done = 0;
    do {
        asm volatile("{\n\t.reg .pred p;\n\t"
            "mbarrier.try_wait.parity.acquire.cluster.shared::cta.b64 p, [%1], %2, 0x989680;\n\t"
            "selp.b32 %0, 1, 0, p;\n\t}"
            : "=r"(done) : "r"(mbar), "r"(parity) : "memory");
    } while(!done);
}

// ===================== Phase 1 (unchanged, verified round 6) =====================
#define P1_XH   0u
#define P1_XL   9216u
#define P1_W1H  18432u
#define P1_W1L  46080u
#define P1_W2H  73728u
#define P1_W2L  101376u
#define P1_BYTES 129024u

__global__ void __launch_bounds__(384,1) phase1_mma(
    const float* __restrict__ x, const float* __restrict__ Ww1,
    const float* __restrict__ Ww2, float* __restrict__ xg)
{
    extern __shared__ char sb[];
    const uint32_t s0 = smem_u32(sb);
    const int tid = threadIdx.x, wid = tid >> 5, lane = tid & 31;

    if (tid < 192){
        const int g = tid >> 6, row = tid & 63;
        float w[64];
        #pragma unroll
        for (int q = 0; q < 16; q++)
            ((float4*)w)[q] = ((const float4*)(Ww1 + tid * 64))[q];
        uint32_t eb = (uint32_t)(g * 4608 + row * 72);
        #pragma unroll
        for (int k = 0; k < 32; k++){
            uint2 hl = split2(w[2*k], w[2*k+1]);
            *(uint32_t*)(sb + P1_W1H + (eb + 2*k)*2) = hl.x;
            *(uint32_t*)(sb + P1_W1L + (eb + 2*k)*2) = hl.y;
        }
        #pragma unroll 4
        for (int b = 0; b < 64; b++) w[b] = Ww2[g * 4096 + b * 64 + row];
        #pragma unroll
        for (int k = 0; k < 32; k++){
            uint2 hl = split2(w[2*k], w[2*k+1]);
            *(uint32_t*)(sb + P1_W2H + (eb + 2*k)*2) = hl.x;
            *(uint32_t*)(sb + P1_W2L + (eb + 2*k)*2) = hl.y;
        }
    }

    const int g  = wid >> 2;
    const int rb = wid & 3;
    const uint32_t w1hB = s0 + P1_W1H + (uint32_t)g * 9216u;
    const uint32_t w1lB = s0 + P1_W1L + (uint32_t)g * 9216u;
    const uint32_t w2hB = s0 + P1_W2H + (uint32_t)g * 9216u;
    const uint32_t w2lB = s0 + P1_W2L + (uint32_t)g * 9216u;

    float4 xr[4];
    const int xi = tid >> 2, xj = (tid & 3) * 16;

    int p = blockIdx.x;
    if (p < NB*LS && tid < 256){
        const float4* s = (const float4*)(x + (size_t)p*4096 + xi*64 + xj);
        xr[0]=s[0]; xr[1]=s[1]; xr[2]=s[2]; xr[3]=s[3];
    }

    for (; p < NB*LS; p += gridDim.x){
        __syncthreads();
        if (tid < 256){
            const float* xf = (const float*)xr;
            uint32_t eb = (uint32_t)(xi * 72 + xj);
            #pragma unroll
            for (int k = 0; k < 8; k++){
                uint2 hl = split2(xf[2*k], xf[2*k+1]);
                *(uint32_t*)(sb + P1_XH + (eb + 2*k)*2) = hl.x;
                *(uint32_t*)(sb + P1_XL + (eb + 2*k)*2) = hl.y;
            }
        }
        __syncthreads();
        int pn = p + gridDim.x;
        if (pn < NB*LS && tid < 256){
            const float4* s = (const float4*)(x + (size_t)pn*4096 + xi*64 + xj);
            xr[0]=s[0]; xr[1]=s[1]; xr[2]=s[2]; xr[3]=s[3];
        }

        float D[8][4];
        #pragma unroll
        for (int t = 0; t < 8; t++){ D[t][0]=D[t][1]=D[t][2]=D[t][3]=0.0f; }
        #pragma unroll
        for (int kc = 0; kc < 4; kc++){
            uint32_t Ah[4], Al[4];
            ldm4(Ah, fraddr(w1hB, rb*16, kc*16, lane));
            ldm4(Al, fraddr(w1lB, rb*16, kc*16, lane));
            #pragma unroll
            for (int nb = 0; nb < 4; nb++){
                uint32_t Bh[4], Bl[4];
                ldm4t(Bh, fraddr(s0 + P1_XH, kc*16, nb*16, lane));
                ldm4t(Bl, fraddr(s0 + P1_XL, kc*16, nb*16, lane));
                mma16816(D[2*nb],   Ah, Bh[0], Bh[1]);
                mma16816(D[2*nb+1], Ah, Bh[2], Bh[3]);
                mma16816(D[2*nb],   Ah, Bl[0], Bl[1]);
                mma16816(D[2*nb+1], Ah, Bl[2], Bl[3]);
                mma16816(D[2*nb],   Al, Bh[0], Bh[1]);
                mma16816(D[2*nb+1], Al, Bh[2], Bh[3]);
            }
        }

        uint32_t A2h[4][4], A2l[4][4];
        #pragma unroll
        for (int kc = 0; kc < 4; kc++){
            uint2 p0 = split2(D[2*kc][0],   D[2*kc][1]);
            uint2 p1 = split2(D[2*kc][2],   D[2*kc][3]);
            uint2 p2 = split2(D[2*kc+1][0], D[2*kc+1][1]);
            uint2 p3 = split2(D[2*kc+1][2], D[2*kc+1][3]);
            A2h[kc][0]=p0.x; A2h[kc][1]=p1.x; A2h[kc][2]=p2.x; A2h[kc][3]=p3.x;
            A2l[kc][0]=p0.y; A2l[kc][1]=p1.y; A2l[kc][2]=p2.y; A2l[kc][3]=p3.y;
        }

        float E[8][4];
        #pragma unroll
        for (int t = 0; t < 8; t++){ E[t][0]=E[t][1]=E[t][2]=E[t][3]=0.0f; }
        #pragma unroll
        for (int kc = 0; kc < 4; kc++){
            #pragma unroll
            for (int nb = 0; nb < 4; nb++){
                uint32_t Bh[4], Bl[4];
                ldm4t(Bh, fraddr(w2hB, kc*16, nb*16, lane));
                ldm4t(Bl, fraddr(w2lB, kc*16, nb*16, lane));
                mma16816(E[2*nb],   A2h[kc], Bh[0], Bh[1]);
                mma16816(E[2*nb+1], A2h[kc], Bh[2], Bh[3]);
                mma16816(E[2*nb],   A2h[kc], Bl[0], Bl[1]);
                mma16816(E[2*nb+1], A2h[kc], Bl[2], Bl[3]);
                mma16816(E[2*nb],   A2l[kc], Bh[0], Bh[1]);
                mma16816(E[2*nb+1], A2l[kc], Bh[2], Bh[3]);
            }
        }

        {
            const int n = p >> 7, l = p & 127;
            float* dst = xg + ((size_t)((l*3+g)*NB + n))*4096;
            const int r0 = rb*16 + (lane >> 2);
            const int cb = (lane & 3) * 2;
            #pragma unroll
            for (int nb = 0; nb < 4; nb++){
                #pragma unroll
                for (int hf = 0; hf < 2; hf++){
                    int t = 2*nb + hf;
                    int b = nb*16 + hf*8 + cb;
                    float* q = dst + r0*64 + b;
                    *(float2*)q          = make_float2(E[t][0], E[t][1]);
                    *(float2*)(q + 8*64) = make_float2(E[t][2], E[t][3]);
                }
            }
        }
    }
}

// ===================== Phase 2 (mma.sync, cluster-2, mbarrier handshake) =====================
#define R2_W2H 36864u
#define R2_W2L 64512u
#define R2_EP  92160u
#define R2_XGS 144384u
#define R2_MB  196608u
#define R2_BYTES 196736u
#define EPS 68
#define EPP 2176
#define XGB 6528

__global__ void __launch_bounds__(384,1) __cluster_dims__(2,1,1) phase2_mma(
    const float* __restrict__ Wu1, const float* __restrict__ Wu2,
    const float* __restrict__ xg, float* __restrict__ out)
{
    extern __shared__ char sb[];
    const uint32_t s0 = smem_u32(sb);
    float* smf = (float*)sb;
    const int tid = threadIdx.x, wid = tid >> 5, lane = tid & 31;
    uint32_t rk; asm("mov.u32 %0, %%cluster_ctarank;" : "=r"(rk));
    const int n  = blockIdx.x >> 1;
    const int A0 = (int)rk * 32;
    const int EPf = 23040, XGSf = 36096;

    // ---- init: Wu2t split ----
    if (tid < 192){
        const int g = tid >> 6, j = tid & 63;
        float w[64];
        #pragma unroll 4
        for (int b = 0; b < 64; b++) w[b] = Wu2[g*4096 + b*64 + j];
        uint32_t eb = (uint32_t)((g*64 + j) * 72);
        #pragma unroll
        for (int k = 0; k < 32; k++){
            uint2 hl = split2(w[2*k], w[2*k+1]);
            *(uint32_t*)(sb + R2_W2H + (eb + 2*k)*2) = hl.x;
            *(uint32_t*)(sb + R2_W2L + (eb + 2*k)*2) = hl.y;
        }
    }
    if (tid < 96){
        const int g = tid >> 5, a = tid & 31;
        float w[64];
        #pragma unroll
        for (int q = 0; q < 16; q++)
            ((float4*)w)[q] = ((const float4*)(Wu1 + (size_t)(g*64 + A0 + a)*64))[q];
        uint32_t eb = (uint32_t)((g*32 + a) * 72);
        #pragma unroll
        for (int k = 0; k < 32; k++){
            uint2 hl = split2(w[2*k], w[2*k+1]);
            *(uint32_t*)(sb + R2_XGS + (eb + 2*k)*2) = hl.x;
            *(uint32_t*)(sb + R2_XGS + 13824u + (eb + 2*k)*2) = hl.y;
        }
    }
    for (int i = tid; i < 9216; i += 384) ((uint32_t*)sb)[i] = 0;
    if (tid == 0)
        asm volatile("mbarrier.init.shared.b64 [%0], %1;" :: "r"(s0 + R2_MB), "r"(256u) : "memory");
    __syncthreads();

    const int g  = wid >> 2;
    const int rb = (wid >> 1) & 1;
    const int jh = wid & 1;
    uint32_t Ah[4][4], Al[4][4];
    #pragma unroll
    for (int kc = 0; kc < 4; kc++){
        ldm4(Ah[kc], fraddr(s0 + R2_XGS + (uint32_t)g*4608u, rb*16, kc*16, lane));
        ldm4(Al[kc], fraddr(s0 + R2_XGS + 13824u + (uint32_t)g*4608u, rb*16, kc*16, lane));
    }
    __syncthreads();

    const uint32_t w2hB = s0 + R2_W2H + (uint32_t)g * 9216u;
    const uint32_t w2lB = s0 + R2_W2L + (uint32_t)g * 9216u;

    const int e_r = tid >> 3, e_c = (tid & 7) * 8;
    float cst[8];
    #pragma unroll
    for (int k = 0; k < 8; k++) cst[k] = 0.0f;

    uint32_t pb, pbar;
    asm("mapa.shared::cluster.u32 %0, %1, %2;" : "=r"(pb) : "r"(s0), "r"(rk^1u));
    asm("mapa.shared::cluster.u32 %0, %1, %2;" : "=r"(pbar) : "r"(s0 + R2_MB), "r"(rk^1u));

    #pragma unroll
    for (int k = 0; k < 4; k++){
        int idx = tid + 384*k;
        int gx = idx / 512, rem = idx & 511;
        int row = rem >> 4, off = rem & 15;
        cpa16(smf + XGSf + gx*EPP + row*EPS + off*4,
              xg + ((size_t)((0*3 + gx)*NB + n))*4096 + (A0+row)*64 + off*4);
    }
    asm volatile("cp.async.commit_group;");

    // both CTAs inited (mbarrier + h buffers) before any peer traffic
    asm volatile("barrier.cluster.arrive.aligned;" ::: "memory");
    asm volatile("barrier.cluster.wait.aligned;" ::: "memory");

    int buf = 0, hb = 0;
    for (int t = 0; t < LS; t++){
        const uint32_t hsH = s0 + (uint32_t)hb*18432u;
        const uint32_t hsL = hsH + 9216u;

        // ---- stage1 (split accumulators: kc01 -> Da, kc23 -> Db) ----
        float Da[4][4], Db[4][4];
        #pragma unroll
        for (int q = 0; q < 4; q++){
            Da[q][0]=Da[q][1]=Da[q][2]=Da[q][3]=0.0f;
            Db[q][0]=Db[q][1]=Db[q][2]=Db[q][3]=0.0f;
        }
        #pragma unroll
        for (int kc = 0; kc < 4; kc++){
            float (*Dp)[4] = (kc < 2) ? Da : Db;
            #pragma unroll
            for (int nb = 0; nb < 2; nb++){
                uint32_t Bh[4], Bl[4];
                ldm4t(Bh, fraddr(hsH, kc*16, (jh*2+nb)*16, lane));
                ldm4t(Bl, fraddr(hsL, kc*16, (jh*2+nb)*16, lane));
                mma16816(Dp[2*nb],   Ah[kc], Bh[0], Bh[1]);
                mma16816(Dp[2*nb+1], Ah[kc], Bh[2], Bh[3]);
                mma16816(Dp[2*nb],   Ah[kc], Bl[0], Bl[1]);
                mma16816(Dp[2*nb+1], Ah[kc], Bl[2], Bl[3]);
                mma16816(Dp[2*nb],   Al[kc], Bh[0], Bh[1]);
                mma16816(Dp[2*nb+1], Al[kc], Bh[2], Bh[3]);
            }
        }
        #pragma unroll
        for (int q = 0; q < 4; q++){
            Da[q][0]+=Db[q][0]; Da[q][1]+=Db[q][1];
            Da[q][2]+=Db[q][2]; Da[q][3]+=Db[q][3];
        }
        // ---- repack ----
        uint32_t A2h[2][4], A2l[2][4];
        #pragma unroll
        for (int c = 0; c < 2; c++){
            uint2 p0 = split2(Da[2*c][0],   Da[2*c][1]);
            uint2 p1 = split2(Da[2*c][2],   Da[2*c][3]);
            uint2 p2 = split2(Da[2*c+1][0], Da[2*c+1][1]);
            uint2 p3 = split2(Da[2*c+1][2], Da[2*c+1][3]);
            A2h[c][0]=p0.x; A2h[c][1]=p1.x; A2h[c][2]=p2.x; A2h[c][3]=p3.x;
            A2l[c][0]=p0.y; A2l[c][1]=p1.y; A2l[c][2]=p2.y; A2l[c][3]=p3.y;
        }
        // ---- stage2 partial ----
        float E[8][4];
        #pragma unroll
        for (int q = 0; q < 8; q++){ E[q][0]=E[q][1]=E[q][2]=E[q][3]=0.0f; }
        #pragma unroll
        for (int c = 0; c < 2; c++){
            #pragma unroll
            for (int nb = 0; nb < 4; nb++){
                uint32_t Bh[4], Bl[4];
                ldm4t(Bh, fraddr(w2hB, jh*32 + c*16, nb*16, lane));
                ldm4t(Bl, fraddr(w2lB, jh*32 + c*16, nb*16, lane));
                mma16816(E[2*nb],   A2h[c], Bh[0], Bh[1]);
                mma16816(E[2*nb+1], A2h[c], Bh[2], Bh[3]);
                mma16816(E[2*nb],   A2h[c], Bl[0], Bl[1]);
                mma16816(E[2*nb+1], A2h[c], Bl[2], Bl[3]);
                mma16816(E[2*nb],   A2l[c], Bh[0], Bh[1]);
                mma16816(E[2*nb+1], A2l[c], Bh[2], Bh[3]);
            }
        }
        // ---- store E partial (padded stride) ----
        {
            float* dst = smf + EPf + (jh*3 + g)*EPP;
            const int r0 = rb*16 + (lane >> 2);
            const int cb = (lane & 3) * 2;
            #pragma unroll
            for (int nb = 0; nb < 4; nb++){
                #pragma unroll
                for (int hf = 0; hf < 2; hf++){
                    int q = 2*nb + hf;
                    int b = nb*16 + hf*8 + cb;
                    float* d2 = dst + r0*EPS + b;
                    *(float2*)d2            = make_float2(E[q][0], E[q][1]);
                    *(float2*)(d2 + 8*EPS)  = make_float2(E[q][2], E[q][3]);
                }
            }
        }
        asm volatile("cp.async.wait_group 0;");
        __syncthreads();                  // E + xg[t] visible

        // ---- epilogue ----
        float hv[8];
        if (tid < 256){
            const int be = e_r*EPS + e_c;
            const float* ep = smf + EPf;
            const float* xb = smf + XGSf + buf*XGB;
            float4 za = *(const float4*)(ep + be);
            float4 zb = *(const float4*)(ep + be + 4);
            float4 zc = *(const float4*)(ep + 3*EPP + be);
            float4 zd = *(const float4*)(ep + 3*EPP + be + 4);
            float4 ze = *(const float4*)(xb + be);
            float4 zf = *(const float4*)(xb + be + 4);
            float4 ra = *(const float4*)(ep + 1*EPP + be);
            float4 rb4= *(const float4*)(ep + 1*EPP + be + 4);
            float4 rc = *(const float4*)(ep + 4*EPP + be);
            float4 rd = *(const float4*)(ep + 4*EPP + be + 4);
            float4 re = *(const float4*)(xb + 1*EPP + be);
            float4 rf = *(const float4*)(xb + 1*EPP + be + 4);
            float4 oa = *(const float4*)(ep + 2*EPP + be);
            float4 ob = *(const float4*)(ep + 2*EPP + be + 4);
            float4 oc = *(const float4*)(ep + 5*EPP + be);
            float4 od = *(const float4*)(ep + 5*EPP + be + 4);
            float4 oe = *(const float4*)(xb + 2*EPP + be);
            float4 of = *(const float4*)(xb + 2*EPP + be + 4);
            float zs[8] = {za.x+zc.x+ze.x, za.y+zc.y+ze.y, za.z+zc.z+ze.z, za.w+zc.w+ze.w,
                           zb.x+zd.x+zf.x, zb.y+zd.y+zf.y, zb.z+zd.z+zf.z, zb.w+zd.w+zf.w};
            float rs[8] = {ra.x+rc.x+re.x, ra.y+rc.y+re.y, ra.z+rc.z+re.z, ra.w+rc.w+re.w,
                           rb4.x+rd.x+rf.x, rb4.y+rd.y+rf.y, rb4.z+rd.z+rf.z, rb4.w+rd.w+rf.w};
            float os[8] = {oa.x+oc.x+oe.x, oa.y+oc.y+oe.y, oa.z+oc.z+oe.z, oa.w+oc.w+oe.w,
                           ob.x+od.x+of.x, ob.y+od.y+of.y, ob.z+od.z+of.z, ob.w+od.w+of.w};
            #pragma unroll
            for (int k = 0; k < 8; k++){
                float z = sigm(zs[k]);
                float r = sigm(rs[k]);
                float o = sigm(os[k]);
                cst[k] = r * (cst[k] + z);
                hv[k] = o * sigm(cst[k]);
            }
            uint32_t hi[4], lo[4];
            #pragma unroll
            for (int k = 0; k < 4; k++){
                uint2 hl = split2(hv[2*k], hv[2*k+1]);
                hi[k] = hl.x; lo[k] = hl.y;
            }
            const uint32_t hwb = (uint32_t)(hb^1)*18432u;
            const uint32_t ho = (uint32_t)(((A0 + e_r)*72 + e_c) * 2);
            *(uint4*)(sb + hwb + ho)         = make_uint4(hi[0],hi[1],hi[2],hi[3]);
            *(uint4*)(sb + hwb + 9216u + ho) = make_uint4(lo[0],lo[1],lo[2],lo[3]);
            uint64_t h01, h23, l01, l23;
            asm("mov.b64 %0, {%1,%2};" : "=l"(h01) : "r"(hi[0]), "r"(hi[1]));
            asm("mov.b64 %0, {%1,%2};" : "=l"(h23) : "r"(hi[2]), "r"(hi[3]));
            asm("mov.b64 %0, {%1,%2};" : "=l"(l01) : "r"(lo[0]), "r"(lo[1]));
            asm("mov.b64 %0, {%1,%2};" : "=l"(l23) : "r"(lo[2]), "r"(lo[3]));
            asm volatile("st.shared::cluster.b64 [%0], %1;" :: "r"(pb + hwb + ho),             "l"(h01));
            asm volatile("st.shared::cluster.b64 [%0], %1;" :: "r"(pb + hwb + ho + 8),         "l"(h23));
            asm volatile("st.shared::cluster.b64 [%0], %1;" :: "r"(pb + hwb + 9216u + ho),     "l"(l01));
            asm volatile("st.shared::cluster.b64 [%0], %1;" :: "r"(pb + hwb + 9216u + ho + 8), "l"(l23));
            // release my peer-h stores to the peer's mbarrier
            asm volatile("mbarrier.arrive.release.cluster.shared::cluster.b64 _, [%0];"
                         :: "r"(pbar) : "memory");
        }

        // overlap: output STG + next xg prefetch before waiting
        if (tid < 256){
            float* od2 = out + ((size_t)(n*LS + t))*4096 + (A0 + e_r)*64 + e_c;
            *(float4*)(od2)   = make_float4(hv[0],hv[1],hv[2],hv[3]);
            *(float4*)(od2+4) = make_float4(hv[4],hv[5],hv[6],hv[7]);
            if (t == LS-1){
                float* hl2 = out + (size_t)NB*LS*4096 + (size_t)n*4096 + (A0 + e_r)*64 + e_c;
                *(float4*)(hl2)   = make_float4(hv[0],hv[1],hv[2],hv[3]);
                *(float4*)(hl2+4) = make_float4(hv[4],hv[5],hv[6],hv[7]);
            }
        }
        if (t + 1 < LS){
            #pragma unroll
            for (int k = 0; k < 4; k++){
                int idx = tid + 384*k;
                int gx = idx / 512, rem = idx & 511;
                int row = rem >> 4, off = rem & 15;
                cpa16(smf + XGSf + (buf^1)*XGB + gx*EPP + row*EPS + off*4,
                      xg + ((size_t)(((t+1)*3 + gx)*NB + n))*4096 + (A0+row)*64 + off*4);
            }
        }
        asm volatile("cp.async.commit_group;");

        __syncthreads();                         // local h visible CTA-wide
        mbar_waitc(s0 + R2_MB, (uint32_t)(t & 1));  // peer h arrived
        buf ^= 1; hb ^= 1;
    }

    // c_last (own rows)
    if (tid < 256){
        float* cl = out + (size_t)NB*LS*4096 + (size_t)NB*4096
                        + (size_t)n*4096 + (A0 + e_r)*64 + e_c;
        *(float4*)(cl)   = make_float4(cst[0],cst[1],cst[2],cst[3]);
        *(float4*)(cl+4) = make_float4(cst[4],cst[5],cst[6],cst[7]);
    }
    // keep cluster alive until both CTAs are fully done (peer stores target my smem)
    asm volatile("barrier.cluster.arrive.aligned;" ::: "memory");
    asm volatile("barrier.cluster.wait.aligned;" ::: "memory");
}

// ---------------------------------------------------------------------------
extern "C" void kernel_launch(void* const* d_in, const int* in_sizes, int n_in,
                              void* d_out, int out_size)
{
    const float* x   = (const float*)d_in[0];
    const float* Ww1 = (const float*)d_in[1];
    const float* Ww2 = (const float*)d_in[2];
    const float* Wu1 = (const float*)d_in[3];
    const float* Wu2 = (const float*)d_in[4];
    float* out = (float*)d_out;

    float* xg = nullptr;
    cudaGetSymbolAddress((void**)&xg, g_xg);

    cudaFuncSetAttribute(phase1_mma, cudaFuncAttributeMaxDynamicSharedMemorySize, (int)P1_BYTES);
    cudaFuncSetAttribute(phase2_mma, cudaFuncAttributeMaxDynamicSharedMemorySize, (int)R2_BYTES);

    phase1_mma<<<148, 384, P1_BYTES>>>(x, Ww1, Ww2, xg);
    phase2_mma<<<2 * NB, 384, R2_BYTES>>>(Wu1, Wu2, xg, out);
}

// round 13
// speedup vs baseline: 1.1224x; 1.1224x over previous
#include <cuda_runtime.h>
#include <cuda_bf16.h>
#include <cstdint>
#include <cstddef>

#define NB 64
#define LS 128

__device__ float g_xg[(size_t)LS*3*NB*4096];

__device__ __forceinline__ float sigm(float x){ return 1.0f/(1.0f+__expf(-x)); }
__device__ __forceinline__ void cpa16(void* dst, const float* src){
    asm volatile("cp.async.ca.shared.global [%0], [%1], 16;"
                 :: "r"((uint32_t)__cvta_generic_to_shared(dst)), "l"(src)); }
__device__ __forceinline__ uint32_t smem_u32(const void* p){
    uint32_t a; asm("{ .reg .u64 t; cvta.to.shared.u64 t, %1; cvt.u32.u64 %0, t; }"
                    : "=r"(a) : "l"(p)); return a; }

// split pair (f0,f1) -> hi bf16x2, lo-residual bf16x2
__device__ __forceinline__ uint2 split2(float f0, float f1){
    __nv_bfloat162 h2 = __floats2bfloat162_rn(f0, f1);
    uint32_t u = *(uint32_t*)&h2;
    float b0 = __uint_as_float(u << 16);
    float b1 = __uint_as_float(u & 0xffff0000u);
    __nv_bfloat162 l2 = __floats2bfloat162_rn(f0 - b0, f1 - b1);
    uint2 r; r.x = u; r.y = *(uint32_t*)&l2;
    return r;
}
__device__ __forceinline__ void ldm4(uint32_t* r, uint32_t addr){
    asm volatile("ldmatrix.sync.aligned.m8n8.x4.shared.b16 {%0,%1,%2,%3}, [%4];"
        : "=r"(r[0]),"=r"(r[1]),"=r"(r[2]),"=r"(r[3]) : "r"(addr));
}
__device__ __forceinline__ void ldm4t(uint32_t* r, uint32_t addr){
    asm volatile("ldmatrix.sync.aligned.m8n8.x4.trans.shared.b16 {%0,%1,%2,%3}, [%4];"
        : "=r"(r[0]),"=r"(r[1]),"=r"(r[2]),"=r"(r[3]) : "r"(addr));
}
__device__ __forceinline__ void mma16816(float* d, const uint32_t* a, uint32_t b0, uint32_t b1){
    asm volatile("mma.sync.aligned.m16n8k16.row.col.f32.bf16.bf16.f32 "
        "{%0,%1,%2,%3}, {%4,%5,%6,%7}, {%8,%9}, {%0,%1,%2,%3};"
        : "+f"(d[0]),"+f"(d[1]),"+f"(d[2]),"+f"(d[3])
        : "r"(a[0]),"r"(a[1]),"r"(a[2]),"r"(a[3]), "r"(b0),"r"(b1));
}
// lane address into 16x16 block of row-major bf16 array, row stride 72 elems
__device__ __forceinline__ uint32_t fraddr(uint32_t base, int row0, int col0, int lane){
    int grp = lane >> 3, lr = lane & 7;
    int row = row0 + lr + (grp & 1) * 8;
    int col = col0 + (grp >> 1) * 8;
    return base + (uint32_t)(row * 72 + col) * 2u;
}
// cluster-scope mbarrier wait (acquire.cluster)
__device__ __forceinline__ void mbar_waitc(uint32_t mbar, uint32_t parity){
    uint32_t done = 0;
    do {
        asm volatile("{\n\t.reg .pred p;\n\t"
            "mbarrier.try_wait.parity.acquire.cluster.shared::cta.b64 p, [%1], %2, 0x989680;\n\t"
            "selp.b32 %0, 1, 0, p;\n\t}"
            : "=r"(done) : "r"(mbar), "r"(parity) : "memory");
    } while(!done);
}

// ===================== Phase 1 (unchanged, verified round 6) =====================
#define P1_XH   0u
#define P1_XL   9216u
#define P1_W1H  18432u
#define P1_W1L  46080u
#define P1_W2H  73728u
#define P1_W2L  101376u
#define P1_BYTES 129024u

__global__ void __launch_bounds__(384,1) phase1_mma(
    const float* __restrict__ x, const float* __restrict__ Ww1,
    const float* __restrict__ Ww2, float* __restrict__ xg)
{
    extern __shared__ char sb[];
    const uint32_t s0 = smem_u32(sb);
    const int tid = threadIdx.x, wid = tid >> 5, lane = tid & 31;

    if (tid < 192){
        const int g = tid >> 6, row = tid & 63;
        float w[64];
        #pragma unroll
        for (int q = 0; q < 16; q++)
            ((float4*)w)[q] = ((const float4*)(Ww1 + tid * 64))[q];
        uint32_t eb = (uint32_t)(g * 4608 + row * 72);
        #pragma unroll
        for (int k = 0; k < 32; k++){
            uint2 hl = split2(w[2*k], w[2*k+1]);
            *(uint32_t*)(sb + P1_W1H + (eb + 2*k)*2) = hl.x;
            *(uint32_t*)(sb + P1_W1L + (eb + 2*k)*2) = hl.y;
        }
        #pragma unroll 4
        for (int b = 0; b < 64; b++) w[b] = Ww2[g * 4096 + b * 64 + row];
        #pragma unroll
        for (int k = 0; k < 32; k++){
            uint2 hl = split2(w[2*k], w[2*k+1]);
            *(uint32_t*)(sb + P1_W2H + (eb + 2*k)*2) = hl.x;
            *(uint32_t*)(sb + P1_W2L + (eb + 2*k)*2) = hl.y;
        }
    }

    const int g  = wid >> 2;
    const int rb = wid & 3;
    const uint32_t w1hB = s0 + P1_W1H + (uint32_t)g * 9216u;
    const uint32_t w1lB = s0 + P1_W1L + (uint32_t)g * 9216u;
    const uint32_t w2hB = s0 + P1_W2H + (uint32_t)g * 9216u;
    const uint32_t w2lB = s0 + P1_W2L + (uint32_t)g * 9216u;

    float4 xr[4];
    const int xi = tid >> 2, xj = (tid & 3) * 16;

    int p = blockIdx.x;
    if (p < NB*LS && tid < 256){
        const float4* s = (const float4*)(x + (size_t)p*4096 + xi*64 + xj);
        xr[0]=s[0]; xr[1]=s[1]; xr[2]=s[2]; xr[3]=s[3];
    }

    for (; p < NB*LS; p += gridDim.x){
        __syncthreads();
        if (tid < 256){
            const float* xf = (const float*)xr;
            uint32_t eb = (uint32_t)(xi * 72 + xj);
            #pragma unroll
            for (int k = 0; k < 8; k++){
                uint2 hl = split2(xf[2*k], xf[2*k+1]);
                *(uint32_t*)(sb + P1_XH + (eb + 2*k)*2) = hl.x;
                *(uint32_t*)(sb + P1_XL + (eb + 2*k)*2) = hl.y;
            }
        }
        __syncthreads();
        int pn = p + gridDim.x;
        if (pn < NB*LS && tid < 256){
            const float4* s = (const float4*)(x + (size_t)pn*4096 + xi*64 + xj);
            xr[0]=s[0]; xr[1]=s[1]; xr[2]=s[2]; xr[3]=s[3];
        }

        float D[8][4];
        #pragma unroll
        for (int t = 0; t < 8; t++){ D[t][0]=D[t][1]=D[t][2]=D[t][3]=0.0f; }
        #pragma unroll
        for (int kc = 0; kc < 4; kc++){
            uint32_t Ah[4], Al[4];
            ldm4(Ah, fraddr(w1hB, rb*16, kc*16, lane));
            ldm4(Al, fraddr(w1lB, rb*16, kc*16, lane));
            #pragma unroll
            for (int nb = 0; nb < 4; nb++){
                uint32_t Bh[4], Bl[4];
                ldm4t(Bh, fraddr(s0 + P1_XH, kc*16, nb*16, lane));
                ldm4t(Bl, fraddr(s0 + P1_XL, kc*16, nb*16, lane));
                mma16816(D[2*nb],   Ah, Bh[0], Bh[1]);
                mma16816(D[2*nb+1], Ah, Bh[2], Bh[3]);
                mma16816(D[2*nb],   Ah, Bl[0], Bl[1]);
                mma16816(D[2*nb+1], Ah, Bl[2], Bl[3]);
                mma16816(D[2*nb],   Al, Bh[0], Bh[1]);
                mma16816(D[2*nb+1], Al, Bh[2], Bh[3]);
            }
        }

        uint32_t A2h[4][4], A2l[4][4];
        #pragma unroll
        for (int kc = 0; kc < 4; kc++){
            uint2 p0 = split2(D[2*kc][0],   D[2*kc][1]);
            uint2 p1 = split2(D[2*kc][2],   D[2*kc][3]);
            uint2 p2 = split2(D[2*kc+1][0], D[2*kc+1][1]);
            uint2 p3 = split2(D[2*kc+1][2], D[2*kc+1][3]);
            A2h[kc][0]=p0.x; A2h[kc][1]=p1.x; A2h[kc][2]=p2.x; A2h[kc][3]=p3.x;
            A2l[kc][0]=p0.y; A2l[kc][1]=p1.y; A2l[kc][2]=p2.y; A2l[kc][3]=p3.y;
        }

        float E[8][4];
        #pragma unroll
        for (int t = 0; t < 8; t++){ E[t][0]=E[t][1]=E[t][2]=E[t][3]=0.0f; }
        #pragma unroll
        for (int kc = 0; kc < 4; kc++){
            #pragma unroll
            for (int nb = 0; nb < 4; nb++){
                uint32_t Bh[4], Bl[4];
                ldm4t(Bh, fraddr(w2hB, kc*16, nb*16, lane));
                ldm4t(Bl, fraddr(w2lB, kc*16, nb*16, lane));
                mma16816(E[2*nb],   A2h[kc], Bh[0], Bh[1]);
                mma16816(E[2*nb+1], A2h[kc], Bh[2], Bh[3]);
                mma16816(E[2*nb],   A2h[kc], Bl[0], Bl[1]);
                mma16816(E[2*nb+1], A2h[kc], Bl[2], Bl[3]);
                mma16816(E[2*nb],   A2l[kc], Bh[0], Bh[1]);
                mma16816(E[2*nb+1], A2l[kc], Bh[2], Bh[3]);
            }
        }

        {
            const int n = p >> 7, l = p & 127;
            float* dst = xg + ((size_t)((l*3+g)*NB + n))*4096;
            const int r0 = rb*16 + (lane >> 2);
            const int cb = (lane & 3) * 2;
            #pragma unroll
            for (int nb = 0; nb < 4; nb++){
                #pragma unroll
                for (int hf = 0; hf < 2; hf++){
                    int t = 2*nb + hf;
                    int b = nb*16 + hf*8 + cb;
                    float* q = dst + r0*64 + b;
                    *(float2*)q          = make_float2(E[t][0], E[t][1]);
                    *(float2*)(q + 8*64) = make_float2(E[t][2], E[t][3]);
                }
            }
        }
    }
}

// ===================== Phase 2 (mma.sync, cluster-2, mbarrier-only h sync) =====================
#define R2_W2H 36864u
#define R2_W2L 64512u
#define R2_EP  92160u
#define R2_XGS 144384u
#define R2_MB  196608u
#define R2_BYTES 196736u
#define EPS 68
#define EPP 2176
#define XGB 6528

__global__ void __launch_bounds__(384,1) __cluster_dims__(2,1,1) phase2_mma(
    const float* __restrict__ Wu1, const float* __restrict__ Wu2,
    const float* __restrict__ xg, float* __restrict__ out)
{
    extern __shared__ char sb[];
    const uint32_t s0 = smem_u32(sb);
    float* smf = (float*)sb;
    const int tid = threadIdx.x, wid = tid >> 5, lane = tid & 31;
    uint32_t rk; asm("mov.u32 %0, %%cluster_ctarank;" : "=r"(rk));
    const int n  = blockIdx.x >> 1;
    const int A0 = (int)rk * 32;
    const int EPf = 23040, XGSf = 36096;

    // ---- init: Wu2t split ----
    if (tid < 192){
        const int g = tid >> 6, j = tid & 63;
        float w[64];
        #pragma unroll 4
        for (int b = 0; b < 64; b++) w[b] = Wu2[g*4096 + b*64 + j];
        uint32_t eb = (uint32_t)((g*64 + j) * 72);
        #pragma unroll
        for (int k = 0; k < 32; k++){
            uint2 hl = split2(w[2*k], w[2*k+1]);
            *(uint32_t*)(sb + R2_W2H + (eb + 2*k)*2) = hl.x;
            *(uint32_t*)(sb + R2_W2L + (eb + 2*k)*2) = hl.y;
        }
    }
    if (tid < 96){
        const int g = tid >> 5, a = tid & 31;
        float w[64];
        #pragma unroll
        for (int q = 0; q < 16; q++)
            ((float4*)w)[q] = ((const float4*)(Wu1 + (size_t)(g*64 + A0 + a)*64))[q];
        uint32_t eb = (uint32_t)((g*32 + a) * 72);
        #pragma unroll
        for (int k = 0; k < 32; k++){
            uint2 hl = split2(w[2*k], w[2*k+1]);
            *(uint32_t*)(sb + R2_XGS + (eb + 2*k)*2) = hl.x;
            *(uint32_t*)(sb + R2_XGS + 13824u + (eb + 2*k)*2) = hl.y;
        }
    }
    for (int i = tid; i < 9216; i += 384) ((uint32_t*)sb)[i] = 0;
    if (tid == 0)
        asm volatile("mbarrier.init.shared.b64 [%0], %1;" :: "r"(s0 + R2_MB), "r"(768u) : "memory");
    __syncthreads();

    const int g  = wid >> 2;
    const int rb = (wid >> 1) & 1;
    const int jh = wid & 1;
    uint32_t Ah[4][4], Al[4][4];
    #pragma unroll
    for (int kc = 0; kc < 4; kc++){
        ldm4(Ah[kc], fraddr(s0 + R2_XGS + (uint32_t)g*4608u, rb*16, kc*16, lane));
        ldm4(Al[kc], fraddr(s0 + R2_XGS + 13824u + (uint32_t)g*4608u, rb*16, kc*16, lane));
    }
    __syncthreads();

    const uint32_t w2hB = s0 + R2_W2H + (uint32_t)g * 9216u;
    const uint32_t w2lB = s0 + R2_W2L + (uint32_t)g * 9216u;

    // epilogue: 512 chunks of 4 cols; thread handles chunk tid and tid+384
    float cst[2][4];
    #pragma unroll
    for (int cc = 0; cc < 2; cc++)
        #pragma unroll
        for (int k = 0; k < 4; k++) cst[cc][k] = 0.0f;

    uint32_t pb, pbar;
    asm("mapa.shared::cluster.u32 %0, %1, %2;" : "=r"(pb) : "r"(s0), "r"(rk^1u));
    asm("mapa.shared::cluster.u32 %0, %1, %2;" : "=r"(pbar) : "r"(s0 + R2_MB), "r"(rk^1u));

    #pragma unroll
    for (int k = 0; k < 4; k++){
        int idx = tid + 384*k;
        int gx = idx / 512, rem = idx & 511;
        int row = rem >> 4, off = rem & 15;
        cpa16(smf + XGSf + gx*EPP + row*EPS + off*4,
              xg + ((size_t)((0*3 + gx)*NB + n))*4096 + (A0+row)*64 + off*4);
    }
    asm volatile("cp.async.commit_group;");

    asm volatile("barrier.cluster.arrive.aligned;" ::: "memory");
    asm volatile("barrier.cluster.wait.aligned;" ::: "memory");

    int buf = 0, hb = 0;
    for (int t = 0; t < LS; t++){
        const uint32_t hsH = s0 + (uint32_t)hb*18432u;
        const uint32_t hsL = hsH + 9216u;

        // ---- stage1 ----
        float Da[4][4], Db[4][4];
        #pragma unroll
        for (int q = 0; q < 4; q++){
            Da[q][0]=Da[q][1]=Da[q][2]=Da[q][3]=0.0f;
            Db[q][0]=Db[q][1]=Db[q][2]=Db[q][3]=0.0f;
        }
        #pragma unroll
        for (int kc = 0; kc < 4; kc++){
            float (*Dp)[4] = (kc < 2) ? Da : Db;
            #pragma unroll
            for (int nb = 0; nb < 2; nb++){
                uint32_t Bh[4], Bl[4];
                ldm4t(Bh, fraddr(hsH, kc*16, (jh*2+nb)*16, lane));
                ldm4t(Bl, fraddr(hsL, kc*16, (jh*2+nb)*16, lane));
                mma16816(Dp[2*nb],   Ah[kc], Bh[0], Bh[1]);
                mma16816(Dp[2*nb+1], Ah[kc], Bh[2], Bh[3]);
                mma16816(Dp[2*nb],   Ah[kc], Bl[0], Bl[1]);
                mma16816(Dp[2*nb+1], Ah[kc], Bl[2], Bl[3]);
                mma16816(Dp[2*nb],   Al[kc], Bh[0], Bh[1]);
                mma16816(Dp[2*nb+1], Al[kc], Bh[2], Bh[3]);
            }
        }
        #pragma unroll
        for (int q = 0; q < 4; q++){
            Da[q][0]+=Db[q][0]; Da[q][1]+=Db[q][1];
            Da[q][2]+=Db[q][2]; Da[q][3]+=Db[q][3];
        }
        uint32_t A2h[2][4], A2l[2][4];
        #pragma unroll
        for (int c = 0; c < 2; c++){
            uint2 p0 = split2(Da[2*c][0],   Da[2*c][1]);
            uint2 p1 = split2(Da[2*c][2],   Da[2*c][3]);
            uint2 p2 = split2(Da[2*c+1][0], Da[2*c+1][1]);
            uint2 p3 = split2(Da[2*c+1][2], Da[2*c+1][3]);
            A2h[c][0]=p0.x; A2h[c][1]=p1.x; A2h[c][2]=p2.x; A2h[c][3]=p3.x;
            A2l[c][0]=p0.y; A2l[c][1]=p1.y; A2l[c][2]=p2.y; A2l[c][3]=p3.y;
        }
        // ---- stage2 partial ----
        float E[8][4];
        #pragma unroll
        for (int q = 0; q < 8; q++){ E[q][0]=E[q][1]=E[q][2]=E[q][3]=0.0f; }
        #pragma unroll
        for (int c = 0; c < 2; c++){
            #pragma unroll
            for (int nb = 0; nb < 4; nb++){
                uint32_t Bh[4], Bl[4];
                ldm4t(Bh, fraddr(w2hB, jh*32 + c*16, nb*16, lane));
                ldm4t(Bl, fraddr(w2lB, jh*32 + c*16, nb*16, lane));
                mma16816(E[2*nb],   A2h[c], Bh[0], Bh[1]);
                mma16816(E[2*nb+1], A2h[c], Bh[2], Bh[3]);
                mma16816(E[2*nb],   A2h[c], Bl[0], Bl[1]);
                mma16816(E[2*nb+1], A2h[c], Bl[2], Bl[3]);
                mma16816(E[2*nb],   A2l[c], Bh[0], Bh[1]);
                mma16816(E[2*nb+1], A2l[c], Bh[2], Bh[3]);
            }
        }
        // ---- store E partial ----
        {
            float* dst = smf + EPf + (jh*3 + g)*EPP;
            const int r0 = rb*16 + (lane >> 2);
            const int cb = (lane & 3) * 2;
            #pragma unroll
            for (int nb = 0; nb < 4; nb++){
                #pragma unroll
                for (int hf = 0; hf < 2; hf++){
                    int q = 2*nb + hf;
                    int b = nb*16 + hf*8 + cb;
                    float* d2 = dst + r0*EPS + b;
                    *(float2*)d2            = make_float2(E[q][0], E[q][1]);
                    *(float2*)(d2 + 8*EPS)  = make_float2(E[q][2], E[q][3]);
                }
            }
        }
        asm volatile("cp.async.wait_group 0;");
        __syncthreads();                  // E + xg[t] visible

        // ---- epilogue: all 384 threads, chunk remap ----
        float hv[2][4];
        const uint32_t hwb = (uint32_t)(hb^1)*18432u;
        #pragma unroll
        for (int cc = 0; cc < 2; cc++){
            int ch = tid + cc*384;
            if (ch < 512){
                int row = ch >> 4, c4 = (ch & 15) * 4;
                int be = row*EPS + c4;
                const float* ep = smf + EPf;
                const float* xb = smf + XGSf + buf*XGB;
                float4 z1 = *(const float4*)(ep + be);
                float4 z2 = *(const float4*)(ep + 3*EPP + be);
                float4 z3 = *(const float4*)(xb + be);
                float4 r1 = *(const float4*)(ep + 1*EPP + be);
                float4 r2 = *(const float4*)(ep + 4*EPP + be);
                float4 r3 = *(const float4*)(xb + 1*EPP + be);
                float4 o1 = *(const float4*)(ep + 2*EPP + be);
                float4 o2 = *(const float4*)(ep + 5*EPP + be);
                float4 o3 = *(const float4*)(xb + 2*EPP + be);
                float zs[4] = {z1.x+z2.x+z3.x, z1.y+z2.y+z3.y, z1.z+z2.z+z3.z, z1.w+z2.w+z3.w};
                float rs[4] = {r1.x+r2.x+r3.x, r1.y+r2.y+r3.y, r1.z+r2.z+r3.z, r1.w+r2.w+r3.w};
                float os[4] = {o1.x+o2.x+o3.x, o1.y+o2.y+o3.y, o1.z+o2.z+o3.z, o1.w+o2.w+o3.w};
                #pragma unroll
                for (int k = 0; k < 4; k++){
                    float z = sigm(zs[k]);
                    float r = sigm(rs[k]);
                    float o = sigm(os[k]);
                    cst[cc][k] = r * (cst[cc][k] + z);
                    hv[cc][k] = o * sigm(cst[cc][k]);
                }
                uint2 p0 = split2(hv[cc][0], hv[cc][1]);
                uint2 p1 = split2(hv[cc][2], hv[cc][3]);
                uint64_t hpk, lpk;
                asm("mov.b64 %0, {%1,%2};" : "=l"(hpk) : "r"(p0.x), "r"(p1.x));
                asm("mov.b64 %0, {%1,%2};" : "=l"(lpk) : "r"(p0.y), "r"(p1.y));
                const uint32_t ho = (uint32_t)(((A0 + row)*72 + c4) * 2);
                *(uint64_t*)(sb + hwb + ho)         = hpk;
                *(uint64_t*)(sb + hwb + 9216u + ho) = lpk;
                asm volatile("st.shared::cluster.b64 [%0], %1;" :: "r"(pb + hwb + ho),          "l"(hpk));
                asm volatile("st.shared::cluster.b64 [%0], %1;" :: "r"(pb + hwb + 9216u + ho),  "l"(lpk));
            }
        }
        // release stores: arrive on both CTAs' mbarriers
        asm volatile("mbarrier.arrive.release.cluster.shared::cluster.b64 _, [%0];"
                     :: "r"(s0 + R2_MB) : "memory");
        asm volatile("mbarrier.arrive.release.cluster.shared::cluster.b64 _, [%0];"
                     :: "r"(pbar) : "memory");

        // overlap: output STG + next xg prefetch before waiting
        #pragma unroll
        for (int cc = 0; cc < 2; cc++){
            int ch = tid + cc*384;
            if (ch < 512){
                int row = ch >> 4, c4 = (ch & 15) * 4;
                float* od2 = out + ((size_t)(n*LS + t))*4096 + (A0 + row)*64 + c4;
                *(float4*)od2 = make_float4(hv[cc][0],hv[cc][1],hv[cc][2],hv[cc][3]);
                if (t == LS-1){
                    float* hl2 = out + (size_t)NB*LS*4096 + (size_t)n*4096 + (A0 + row)*64 + c4;
                    *(float4*)hl2 = make_float4(hv[cc][0],hv[cc][1],hv[cc][2],hv[cc][3]);
                }
            }
        }
        if (t + 1 < LS){
            #pragma unroll
            for (int k = 0; k < 4; k++){
                int idx = tid + 384*k;
                int gx = idx / 512, rem = idx & 511;
                int row = rem >> 4, off = rem & 15;
                cpa16(smf + XGSf + (buf^1)*XGB + gx*EPP + row*EPS + off*4,
                      xg + ((size_t)(((t+1)*3 + gx)*NB + n))*4096 + (A0+row)*64 + off*4);
            }
        }
        asm volatile("cp.async.commit_group;");

        mbar_waitc(s0 + R2_MB, (uint32_t)(t & 1));  // all h (local + peer) arrived
        buf ^= 1; hb ^= 1;
    }

    // c_last
    #pragma unroll
    for (int cc = 0; cc < 2; cc++){
        int ch = tid + cc*384;
        if (ch < 512){
            int row = ch >> 4, c4 = (ch & 15) * 4;
            float* cl = out + (size_t)NB*LS*4096 + (size_t)NB*4096
                            + (size_t)n*4096 + (A0 + row)*64 + c4;
            *(float4*)cl = make_float4(cst[cc][0],cst[cc][1],cst[cc][2],cst[cc][3]);
        }
    }
    asm volatile("barrier.cluster.arrive.aligned;" ::: "memory");
    asm volatile("barrier.cluster.wait.aligned;" ::: "memory");
}

// ---------------------------------------------------------------------------
extern "C" void kernel_launch(void* const* d_in, const int* in_sizes, int n_in,
                              void* d_out, int out_size)
{
    const float* x   = (const float*)d_in[0];
    const float* Ww1 = (const float*)d_in[1];
    const float* Ww2 = (const float*)d_in[2];
    const float* Wu1 = (const float*)d_in[3];
    const float* Wu2 = (const float*)d_in[4];
    float* out = (float*)d_out;

    float* xg = nullptr;
    cudaGetSymbolAddress((void**)&xg, g_xg);

    cudaFuncSetAttribute(phase1_mma, cudaFuncAttributeMaxDynamicSharedMemorySize, (int)P1_BYTES);
    cudaFuncSetAttribute(phase2_mma, cudaFuncAttributeMaxDynamicSharedMemorySize, (int)R2_BYTES);

    phase1_mma<<<148, 384, P1_BYTES>>>(x, Ww1, Ww2, xg);
    phase2_mma<<<2 * NB, 384, R2_BYTES>>>(Wu1, Wu2, xg, out);
}

// round 14
// speedup vs baseline: 1.1782x; 1.0497x over previous
#include <cuda_runtime.h>
#include <cuda_bf16.h>
#include <cstdint>
#include <cstddef>

#define NB 64
#define LS 128

__device__ float g_xg[(size_t)LS*3*NB*4096];

__device__ __forceinline__ float sigm(float x){ return 1.0f/(1.0f+__expf(-x)); }
__device__ __forceinline__ void cpa16(void* dst, const float* src){
    asm volatile("cp.async.ca.shared.global [%0], [%1], 16;"
                 :: "r"((uint32_t)__cvta_generic_to_shared(dst)), "l"(src)); }
__device__ __forceinline__ uint32_t smem_u32(const void* p){
    uint32_t a; asm("{ .reg .u64 t; cvta.to.shared.u64 t, %1; cvt.u32.u64 %0, t; }"
                    : "=r"(a) : "l"(p)); return a; }

// split pair (f0,f1) -> hi bf16x2, lo-residual bf16x2
__device__ __forceinline__ uint2 split2(float f0, float f1){
    __nv_bfloat162 h2 = __floats2bfloat162_rn(f0, f1);
    uint32_t u = *(uint32_t*)&h2;
    float b0 = __uint_as_float(u << 16);
    float b1 = __uint_as_float(u & 0xffff0000u);
    __nv_bfloat162 l2 = __floats2bfloat162_rn(f0 - b0, f1 - b1);
    uint2 r; r.x = u; r.y = *(uint32_t*)&l2;
    return r;
}
__device__ __forceinline__ void ldm4(uint32_t* r, uint32_t addr){
    asm volatile("ldmatrix.sync.aligned.m8n8.x4.shared.b16 {%0,%1,%2,%3}, [%4];"
        : "=r"(r[0]),"=r"(r[1]),"=r"(r[2]),"=r"(r[3]) : "r"(addr));
}
__device__ __forceinline__ void ldm4t(uint32_t* r, uint32_t addr){
    asm volatile("ldmatrix.sync.aligned.m8n8.x4.trans.shared.b16 {%0,%1,%2,%3}, [%4];"
        : "=r"(r[0]),"=r"(r[1]),"=r"(r[2]),"=r"(r[3]) : "r"(addr));
}
__device__ __forceinline__ void mma16816(float* d, const uint32_t* a, uint32_t b0, uint32_t b1){
    asm volatile("mma.sync.aligned.m16n8k16.row.col.f32.bf16.bf16.f32 "
        "{%0,%1,%2,%3}, {%4,%5,%6,%7}, {%8,%9}, {%0,%1,%2,%3};"
        : "+f"(d[0]),"+f"(d[1]),"+f"(d[2]),"+f"(d[3])
        : "r"(a[0]),"r"(a[1]),"r"(a[2]),"r"(a[3]), "r"(b0),"r"(b1));
}
// lane address into 16x16 block of row-major bf16 array, row stride 72 elems
__device__ __forceinline__ uint32_t fraddr(uint32_t base, int row0, int col0, int lane){
    int grp = lane >> 3, lr = lane & 7;
    int row = row0 + lr + (grp & 1) * 8;
    int col = col0 + (grp >> 1) * 8;
    return base + (uint32_t)(row * 72 + col) * 2u;
}
// cluster-scope mbarrier wait (acquire.cluster)
__device__ __forceinline__ void mbar_waitc(uint32_t mbar, uint32_t parity){
    uint32_t done = 0;
    do {
        asm volatile("{\n\t.reg .pred p;\n\t"
            "mbarrier.try_wait.parity.acquire.cluster.shared::cta.b64 p, [%1], %2, 0x989680;\n\t"
            "selp.b32 %0, 1, 0, p;\n\t}"
            : "=r"(done) : "r"(mbar), "r"(parity) : "memory");
    } while(!done);
}

// ===================== Phase 1 (unchanged, verified round 6) =====================
#define P1_XH   0u
#define P1_XL   9216u
#define P1_W1H  18432u
#define P1_W1L  46080u
#define P1_W2H  73728u
#define P1_W2L  101376u
#define P1_BYTES 129024u

__global__ void __launch_bounds__(384,1) phase1_mma(
    const float* __restrict__ x, const float* __restrict__ Ww1,
    const float* __restrict__ Ww2, float* __restrict__ xg)
{
    extern __shared__ char sb[];
    const uint32_t s0 = smem_u32(sb);
    const int tid = threadIdx.x, wid = tid >> 5, lane = tid & 31;

    if (tid < 192){
        const int g = tid >> 6, row = tid & 63;
        float w[64];
        #pragma unroll
        for (int q = 0; q < 16; q++)
            ((float4*)w)[q] = ((const float4*)(Ww1 + tid * 64))[q];
        uint32_t eb = (uint32_t)(g * 4608 + row * 72);
        #pragma unroll
        for (int k = 0; k < 32; k++){
            uint2 hl = split2(w[2*k], w[2*k+1]);
            *(uint32_t*)(sb + P1_W1H + (eb + 2*k)*2) = hl.x;
            *(uint32_t*)(sb + P1_W1L + (eb + 2*k)*2) = hl.y;
        }
        #pragma unroll 4
        for (int b = 0; b < 64; b++) w[b] = Ww2[g * 4096 + b * 64 + row];
        #pragma unroll
        for (int k = 0; k < 32; k++){
            uint2 hl = split2(w[2*k], w[2*k+1]);
            *(uint32_t*)(sb + P1_W2H + (eb + 2*k)*2) = hl.x;
            *(uint32_t*)(sb + P1_W2L + (eb + 2*k)*2) = hl.y;
        }
    }

    const int g  = wid >> 2;
    const int rb = wid & 3;
    const uint32_t w1hB = s0 + P1_W1H + (uint32_t)g * 9216u;
    const uint32_t w1lB = s0 + P1_W1L + (uint32_t)g * 9216u;
    const uint32_t w2hB = s0 + P1_W2H + (uint32_t)g * 9216u;
    const uint32_t w2lB = s0 + P1_W2L + (uint32_t)g * 9216u;

    float4 xr[4];
    const int xi = tid >> 2, xj = (tid & 3) * 16;

    int p = blockIdx.x;
    if (p < NB*LS && tid < 256){
        const float4* s = (const float4*)(x + (size_t)p*4096 + xi*64 + xj);
        xr[0]=s[0]; xr[1]=s[1]; xr[2]=s[2]; xr[3]=s[3];
    }

    for (; p < NB*LS; p += gridDim.x){
        __syncthreads();
        if (tid < 256){
            const float* xf = (const float*)xr;
            uint32_t eb = (uint32_t)(xi * 72 + xj);
            #pragma unroll
            for (int k = 0; k < 8; k++){
                uint2 hl = split2(xf[2*k], xf[2*k+1]);
                *(uint32_t*)(sb + P1_XH + (eb + 2*k)*2) = hl.x;
                *(uint32_t*)(sb + P1_XL + (eb + 2*k)*2) = hl.y;
            }
        }
        __syncthreads();
        int pn = p + gridDim.x;
        if (pn < NB*LS && tid < 256){
            const float4* s = (const float4*)(x + (size_t)pn*4096 + xi*64 + xj);
            xr[0]=s[0]; xr[1]=s[1]; xr[2]=s[2]; xr[3]=s[3];
        }

        float D[8][4];
        #pragma unroll
        for (int t = 0; t < 8; t++){ D[t][0]=D[t][1]=D[t][2]=D[t][3]=0.0f; }
        #pragma unroll
        for (int kc = 0; kc < 4; kc++){
            uint32_t Ah[4], Al[4];
            ldm4(Ah, fraddr(w1hB, rb*16, kc*16, lane));
            ldm4(Al, fraddr(w1lB, rb*16, kc*16, lane));
            #pragma unroll
            for (int nb = 0; nb < 4; nb++){
                uint32_t Bh[4], Bl[4];
                ldm4t(Bh, fraddr(s0 + P1_XH, kc*16, nb*16, lane));
                ldm4t(Bl, fraddr(s0 + P1_XL, kc*16, nb*16, lane));
                mma16816(D[2*nb],   Ah, Bh[0], Bh[1]);
                mma16816(D[2*nb+1], Ah, Bh[2], Bh[3]);
                mma16816(D[2*nb],   Ah, Bl[0], Bl[1]);
                mma16816(D[2*nb+1], Ah, Bl[2], Bl[3]);
                mma16816(D[2*nb],   Al, Bh[0], Bh[1]);
                mma16816(D[2*nb+1], Al, Bh[2], Bh[3]);
            }
        }

        uint32_t A2h[4][4], A2l[4][4];
        #pragma unroll
        for (int kc = 0; kc < 4; kc++){
            uint2 p0 = split2(D[2*kc][0],   D[2*kc][1]);
            uint2 p1 = split2(D[2*kc][2],   D[2*kc][3]);
            uint2 p2 = split2(D[2*kc+1][0], D[2*kc+1][1]);
            uint2 p3 = split2(D[2*kc+1][2], D[2*kc+1][3]);
            A2h[kc][0]=p0.x; A2h[kc][1]=p1.x; A2h[kc][2]=p2.x; A2h[kc][3]=p3.x;
            A2l[kc][0]=p0.y; A2l[kc][1]=p1.y; A2l[kc][2]=p2.y; A2l[kc][3]=p3.y;
        }

        float E[8][4];
        #pragma unroll
        for (int t = 0; t < 8; t++){ E[t][0]=E[t][1]=E[t][2]=E[t][3]=0.0f; }
        #pragma unroll
        for (int kc = 0; kc < 4; kc++){
            #pragma unroll
            for (int nb = 0; nb < 4; nb++){
                uint32_t Bh[4], Bl[4];
                ldm4t(Bh, fraddr(w2hB, kc*16, nb*16, lane));
                ldm4t(Bl, fraddr(w2lB, kc*16, nb*16, lane));
                mma16816(E[2*nb],   A2h[kc], Bh[0], Bh[1]);
                mma16816(E[2*nb+1], A2h[kc], Bh[2], Bh[3]);
                mma16816(E[2*nb],   A2h[kc], Bl[0], Bl[1]);
                mma16816(E[2*nb+1], A2h[kc], Bl[2], Bl[3]);
                mma16816(E[2*nb],   A2l[kc], Bh[0], Bh[1]);
                mma16816(E[2*nb+1], A2l[kc], Bh[2], Bh[3]);
            }
        }

        {
            const int n = p >> 7, l = p & 127;
            float* dst = xg + ((size_t)((l*3+g)*NB + n))*4096;
            const int r0 = rb*16 + (lane >> 2);
            const int cb = (lane & 3) * 2;
            #pragma unroll
            for (int nb = 0; nb < 4; nb++){
                #pragma unroll
                for (int hf = 0; hf < 2; hf++){
                    int t = 2*nb + hf;
                    int b = nb*16 + hf*8 + cb;
                    float* q = dst + r0*64 + b;
                    *(float2*)q          = make_float2(E[t][0], E[t][1]);
                    *(float2*)(q + 8*64) = make_float2(E[t][2], E[t][3]);
                }
            }
        }
    }
}

// ===================== Phase 2 (mma.sync, cluster-2, single-bf16 h state) =====================
// HB0 0 (9216) | HB1 9216 | W2H 18432 (27648) | W2L 46080 (27648)
// EP 73728 (52224) | XGS 125952 (52224) | MB 178176
#define S2_W2H 18432u
#define S2_W2L 46080u
#define S2_EP  73728u
#define S2_XGS 125952u
#define S2_MB  178176u
#define S2_BYTES 178304u
#define EPS 68
#define EPP 2176
#define XGB 6528

__global__ void __launch_bounds__(384,1) __cluster_dims__(2,1,1) phase2_mma(
    const float* __restrict__ Wu1, const float* __restrict__ Wu2,
    const float* __restrict__ xg, float* __restrict__ out)
{
    extern __shared__ char sb[];
    const uint32_t s0 = smem_u32(sb);
    float* smf = (float*)sb;
    const int tid = threadIdx.x, wid = tid >> 5, lane = tid & 31;
    uint32_t rk; asm("mov.u32 %0, %%cluster_ctarank;" : "=r"(rk));
    const int n  = blockIdx.x >> 1;
    const int A0 = (int)rk * 32;
    const int EPf = 18432, XGSf = 31488;

    // ---- init: Wu2t split ----
    if (tid < 192){
        const int g = tid >> 6, j = tid & 63;
        float w[64];
        #pragma unroll 4
        for (int b = 0; b < 64; b++) w[b] = Wu2[g*4096 + b*64 + j];
        uint32_t eb = (uint32_t)((g*64 + j) * 72);
        #pragma unroll
        for (int k = 0; k < 32; k++){
            uint2 hl = split2(w[2*k], w[2*k+1]);
            *(uint32_t*)(sb + S2_W2H + (eb + 2*k)*2) = hl.x;
            *(uint32_t*)(sb + S2_W2L + (eb + 2*k)*2) = hl.y;
        }
    }
    // Wu1 own rows split into temp (XGS area)
    if (tid < 96){
        const int g = tid >> 5, a = tid & 31;
        float w[64];
        #pragma unroll
        for (int q = 0; q < 16; q++)
            ((float4*)w)[q] = ((const float4*)(Wu1 + (size_t)(g*64 + A0 + a)*64))[q];
        uint32_t eb = (uint32_t)((g*32 + a) * 72);
        #pragma unroll
        for (int k = 0; k < 32; k++){
            uint2 hl = split2(w[2*k], w[2*k+1]);
            *(uint32_t*)(sb + S2_XGS + (eb + 2*k)*2) = hl.x;
            *(uint32_t*)(sb + S2_XGS + 13824u + (eb + 2*k)*2) = hl.y;
        }
    }
    // zero both h buffers (2 x 9216 B)
    for (int i = tid; i < 4608; i += 384) ((uint32_t*)sb)[i] = 0;
    if (tid == 0)
        asm volatile("mbarrier.init.shared.b64 [%0], %1;" :: "r"(s0 + S2_MB), "r"(768u) : "memory");
    __syncthreads();

    const int g  = wid >> 2;
    const int rb = (wid >> 1) & 1;
    const int jh = wid & 1;
    uint32_t Ah[4][4], Al[4][4];
    #pragma unroll
    for (int kc = 0; kc < 4; kc++){
        ldm4(Ah[kc], fraddr(s0 + S2_XGS + (uint32_t)g*4608u, rb*16, kc*16, lane));
        ldm4(Al[kc], fraddr(s0 + S2_XGS + 13824u + (uint32_t)g*4608u, rb*16, kc*16, lane));
    }
    __syncthreads();

    const uint32_t w2hB = s0 + S2_W2H + (uint32_t)g * 9216u;
    const uint32_t w2lB = s0 + S2_W2L + (uint32_t)g * 9216u;

    float cst[2][4];
    #pragma unroll
    for (int cc = 0; cc < 2; cc++)
        #pragma unroll
        for (int k = 0; k < 4; k++) cst[cc][k] = 0.0f;

    uint32_t pb, pbar;
    asm("mapa.shared::cluster.u32 %0, %1, %2;" : "=r"(pb) : "r"(s0), "r"(rk^1u));
    asm("mapa.shared::cluster.u32 %0, %1, %2;" : "=r"(pbar) : "r"(s0 + S2_MB), "r"(rk^1u));

    #pragma unroll
    for (int k = 0; k < 4; k++){
        int idx = tid + 384*k;
        int gx = idx / 512, rem = idx & 511;
        int row = rem >> 4, off = rem & 15;
        cpa16(smf + XGSf + gx*EPP + row*EPS + off*4,
              xg + ((size_t)((0*3 + gx)*NB + n))*4096 + (A0+row)*64 + off*4);
    }
    asm volatile("cp.async.commit_group;");

    asm volatile("barrier.cluster.arrive.aligned;" ::: "memory");
    asm volatile("barrier.cluster.wait.aligned;" ::: "memory");

    int buf = 0, hb = 0;
    for (int t = 0; t < LS; t++){
        const uint32_t hsB = s0 + (uint32_t)hb*9216u;

        // ---- stage1 (h single-bf16; split accumulators) ----
        float Da[4][4], Db[4][4];
        #pragma unroll
        for (int q = 0; q < 4; q++){
            Da[q][0]=Da[q][1]=Da[q][2]=Da[q][3]=0.0f;
            Db[q][0]=Db[q][1]=Db[q][2]=Db[q][3]=0.0f;
        }
        #pragma unroll
        for (int kc = 0; kc < 4; kc++){
            float (*Dp)[4] = (kc < 2) ? Da : Db;
            #pragma unroll
            for (int nb = 0; nb < 2; nb++){
                uint32_t Bh[4];
                ldm4t(Bh, fraddr(hsB, kc*16, (jh*2+nb)*16, lane));
                mma16816(Dp[2*nb],   Ah[kc], Bh[0], Bh[1]);
                mma16816(Dp[2*nb+1], Ah[kc], Bh[2], Bh[3]);
                mma16816(Dp[2*nb],   Al[kc], Bh[0], Bh[1]);
                mma16816(Dp[2*nb+1], Al[kc], Bh[2], Bh[3]);
            }
        }
        #pragma unroll
        for (int q = 0; q < 4; q++){
            Da[q][0]+=Db[q][0]; Da[q][1]+=Db[q][1];
            Da[q][2]+=Db[q][2]; Da[q][3]+=Db[q][3];
        }
        uint32_t A2h[2][4], A2l[2][4];
        #pragma unroll
        for (int c = 0; c < 2; c++){
            uint2 p0 = split2(Da[2*c][0],   Da[2*c][1]);
            uint2 p1 = split2(Da[2*c][2],   Da[2*c][3]);
            uint2 p2 = split2(Da[2*c+1][0], Da[2*c+1][1]);
            uint2 p3 = split2(Da[2*c+1][2], Da[2*c+1][3]);
            A2h[c][0]=p0.x; A2h[c][1]=p1.x; A2h[c][2]=p2.x; A2h[c][3]=p3.x;
            A2l[c][0]=p0.y; A2l[c][1]=p1.y; A2l[c][2]=p2.y; A2l[c][3]=p3.y;
        }
        // ---- stage2 partial (T keeps 2-term split) ----
        float E[8][4];
        #pragma unroll
        for (int q = 0; q < 8; q++){ E[q][0]=E[q][1]=E[q][2]=E[q][3]=0.0f; }
        #pragma unroll
        for (int c = 0; c < 2; c++){
            #pragma unroll
            for (int nb = 0; nb < 4; nb++){
                uint32_t Bh[4], Bl[4];
                ldm4t(Bh, fraddr(w2hB, jh*32 + c*16, nb*16, lane));
                ldm4t(Bl, fraddr(w2lB, jh*32 + c*16, nb*16, lane));
                mma16816(E[2*nb],   A2h[c], Bh[0], Bh[1]);
                mma16816(E[2*nb+1], A2h[c], Bh[2], Bh[3]);
                mma16816(E[2*nb],   A2h[c], Bl[0], Bl[1]);
                mma16816(E[2*nb+1], A2h[c], Bl[2], Bl[3]);
                mma16816(E[2*nb],   A2l[c], Bh[0], Bh[1]);
                mma16816(E[2*nb+1], A2l[c], Bh[2], Bh[3]);
            }
        }
        // ---- store E partial ----
        {
            float* dst = smf + EPf + (jh*3 + g)*EPP;
            const int r0 = rb*16 + (lane >> 2);
            const int cb = (lane & 3) * 2;
            #pragma unroll
            for (int nb = 0; nb < 4; nb++){
                #pragma unroll
                for (int hf = 0; hf < 2; hf++){
                    int q = 2*nb + hf;
                    int b = nb*16 + hf*8 + cb;
                    float* d2 = dst + r0*EPS + b;
                    *(float2*)d2            = make_float2(E[q][0], E[q][1]);
                    *(float2*)(d2 + 8*EPS)  = make_float2(E[q][2], E[q][3]);
                }
            }
        }
        asm volatile("cp.async.wait_group 0;");
        __syncthreads();                  // E + xg[t] visible

        // ---- epilogue: all 384 threads, chunk remap; h -> single bf16 ----
        float hv[2][4];
        const uint32_t hwb = (uint32_t)(hb^1)*9216u;
        #pragma unroll
        for (int cc = 0; cc < 2; cc++){
            int ch = tid + cc*384;
            if (ch < 512){
                int row = ch >> 4, c4 = (ch & 15) * 4;
                int be = row*EPS + c4;
                const float* ep = smf + EPf;
                const float* xb = smf + XGSf + buf*XGB;
                float4 z1 = *(const float4*)(ep + be);
                float4 z2 = *(const float4*)(ep + 3*EPP + be);
                float4 z3 = *(const float4*)(xb + be);
                float4 r1 = *(const float4*)(ep + 1*EPP + be);
                float4 r2 = *(const float4*)(ep + 4*EPP + be);
                float4 r3 = *(const float4*)(xb + 1*EPP + be);
                float4 o1 = *(const float4*)(ep + 2*EPP + be);
                float4 o2 = *(const float4*)(ep + 5*EPP + be);
                float4 o3 = *(const float4*)(xb + 2*EPP + be);
                float zs[4] = {z1.x+z2.x+z3.x, z1.y+z2.y+z3.y, z1.z+z2.z+z3.z, z1.w+z2.w+z3.w};
                float rs[4] = {r1.x+r2.x+r3.x, r1.y+r2.y+r3.y, r1.z+r2.z+r3.z, r1.w+r2.w+r3.w};
                float os[4] = {o1.x+o2.x+o3.x, o1.y+o2.y+o3.y, o1.z+o2.z+o3.z, o1.w+o2.w+o3.w};
                #pragma unroll
                for (int k = 0; k < 4; k++){
                    float z = sigm(zs[k]);
                    float r = sigm(rs[k]);
                    float o = sigm(os[k]);
                    cst[cc][k] = r * (cst[cc][k] + z);
                    hv[cc][k] = o * sigm(cst[cc][k]);
                }
                __nv_bfloat162 b01 = __floats2bfloat162_rn(hv[cc][0], hv[cc][1]);
                __nv_bfloat162 b23 = __floats2bfloat162_rn(hv[cc][2], hv[cc][3]);
                uint32_t u01 = *(uint32_t*)&b01, u23 = *(uint32_t*)&b23;
                uint64_t hpk;
                asm("mov.b64 %0, {%1,%2};" : "=l"(hpk) : "r"(u01), "r"(u23));
                const uint32_t ho = (uint32_t)(((A0 + row)*72 + c4) * 2);
                *(uint64_t*)(sb + hwb + ho) = hpk;
                asm volatile("st.shared::cluster.b64 [%0], %1;" :: "r"(pb + hwb + ho), "l"(hpk));
            }
        }
        asm volatile("mbarrier.arrive.release.cluster.shared::cluster.b64 _, [%0];"
                     :: "r"(s0 + S2_MB) : "memory");
        asm volatile("mbarrier.arrive.release.cluster.shared::cluster.b64 _, [%0];"
                     :: "r"(pbar) : "memory");

        // overlap: output STG + next xg prefetch before waiting
        #pragma unroll
        for (int cc = 0; cc < 2; cc++){
            int ch = tid + cc*384;
            if (ch < 512){
                int row = ch >> 4, c4 = (ch & 15) * 4;
                float* od2 = out + ((size_t)(n*LS + t))*4096 + (A0 + row)*64 + c4;
                *(float4*)od2 = make_float4(hv[cc][0],hv[cc][1],hv[cc][2],hv[cc][3]);
                if (t == LS-1){
                    float* hl2 = out + (size_t)NB*LS*4096 + (size_t)n*4096 + (A0 + row)*64 + c4;
                    *(float4*)hl2 = make_float4(hv[cc][0],hv[cc][1],hv[cc][2],hv[cc][3]);
                }
            }
        }
        if (t + 1 < LS){
            #pragma unroll
            for (int k = 0; k < 4; k++){
                int idx = tid + 384*k;
                int gx = idx / 512, rem = idx & 511;
                int row = rem >> 4, off = rem & 15;
                cpa16(smf + XGSf + (buf^1)*XGB + gx*EPP + row*EPS + off*4,
                      xg + ((size_t)(((t+1)*3 + gx)*NB + n))*4096 + (A0+row)*64 + off*4);
            }
        }
        asm volatile("cp.async.commit_group;");

        mbar_waitc(s0 + S2_MB, (uint32_t)(t & 1));
        buf ^= 1; hb ^= 1;
    }

    // c_last
    #pragma unroll
    for (int cc = 0; cc < 2; cc++){
        int ch = tid + cc*384;
        if (ch < 512){
            int row = ch >> 4, c4 = (ch & 15) * 4;
            float* cl = out + (size_t)NB*LS*4096 + (size_t)NB*4096
                            + (size_t)n*4096 + (A0 + row)*64 + c4;
            *(float4*)cl = make_float4(cst[cc][0],cst[cc][1],cst[cc][2],cst[cc][3]);
        }
    }
    asm volatile("barrier.cluster.arrive.aligned;" ::: "memory");
    asm volatile("barrier.cluster.wait.aligned;" ::: "memory");
}

// ---------------------------------------------------------------------------
extern "C" void kernel_launch(void* const* d_in, const int* in_sizes, int n_in,
                              void* d_out, int out_size)
{
    const float* x   = (const float*)d_in[0];
    const float* Ww1 = (const float*)d_in[1];
    const float* Ww2 = (const float*)d_in[2];
    const float* Wu1 = (const float*)d_in[3];
    const float* Wu2 = (const float*)d_in[4];
    float* out = (float*)d_out;

    float* xg = nullptr;
    cudaGetSymbolAddress((void**)&xg, g_xg);

    cudaFuncSetAttribute(phase1_mma, cudaFuncAttributeMaxDynamicSharedMemorySize, (int)P1_BYTES);
    cudaFuncSetAttribute(phase2_mma, cudaFuncAttributeMaxDynamicSharedMemorySize, (int)S2_BYTES);

    phase1_mma<<<148, 384, P1_BYTES>>>(x, Ww1, Ww2, xg);
    phase2_mma<<<2 * NB, 384, S2_BYTES>>>(Wu1, Wu2, xg, out);
}

// round 15
// speedup vs baseline: 1.2761x; 1.0831x over previous
#include <cuda_runtime.h>
#include <cuda_bf16.h>
#include <cstdint>
#include <cstddef>

#define NB 64
#define LS 128

__device__ float g_xg[(size_t)LS*3*NB*4096];

__device__ __forceinline__ float sigm(float x){ return 1.0f/(1.0f+__expf(-x)); }
__device__ __forceinline__ void cpa16(void* dst, const float* src){
    asm volatile("cp.async.ca.shared.global [%0], [%1], 16;"
                 :: "r"((uint32_t)__cvta_generic_to_shared(dst)), "l"(src)); }
__device__ __forceinline__ uint32_t smem_u32(const void* p){
    uint32_t a; asm("{ .reg .u64 t; cvta.to.shared.u64 t, %1; cvt.u32.u64 %0, t; }"
                    : "=r"(a) : "l"(p)); return a; }

// split pair (f0,f1) -> hi bf16x2, lo-residual bf16x2
__device__ __forceinline__ uint2 split2(float f0, float f1){
    __nv_bfloat162 h2 = __floats2bfloat162_rn(f0, f1);
    uint32_t u = *(uint32_t*)&h2;
    float b0 = __uint_as_float(u << 16);
    float b1 = __uint_as_float(u & 0xffff0000u);
    __nv_bfloat162 l2 = __floats2bfloat162_rn(f0 - b0, f1 - b1);
    uint2 r; r.x = u; r.y = *(uint32_t*)&l2;
    return r;
}
__device__ __forceinline__ uint32_t cvt2(float f0, float f1){
    __nv_bfloat162 h2 = __floats2bfloat162_rn(f0, f1);
    return *(uint32_t*)&h2;
}
__device__ __forceinline__ void ldm4(uint32_t* r, uint32_t addr){
    asm volatile("ldmatrix.sync.aligned.m8n8.x4.shared.b16 {%0,%1,%2,%3}, [%4];"
        : "=r"(r[0]),"=r"(r[1]),"=r"(r[2]),"=r"(r[3]) : "r"(addr));
}
__device__ __forceinline__ void ldm4t(uint32_t* r, uint32_t addr){
    asm volatile("ldmatrix.sync.aligned.m8n8.x4.trans.shared.b16 {%0,%1,%2,%3}, [%4];"
        : "=r"(r[0]),"=r"(r[1]),"=r"(r[2]),"=r"(r[3]) : "r"(addr));
}
__device__ __forceinline__ void mma16816(float* d, const uint32_t* a, uint32_t b0, uint32_t b1){
    asm volatile("mma.sync.aligned.m16n8k16.row.col.f32.bf16.bf16.f32 "
        "{%0,%1,%2,%3}, {%4,%5,%6,%7}, {%8,%9}, {%0,%1,%2,%3};"
        : "+f"(d[0]),"+f"(d[1]),"+f"(d[2]),"+f"(d[3])
        : "r"(a[0]),"r"(a[1]),"r"(a[2]),"r"(a[3]), "r"(b0),"r"(b1));
}
// lane address into 16x16 block of row-major bf16 array, row stride 72 elems
__device__ __forceinline__ uint32_t fraddr(uint32_t base, int row0, int col0, int lane){
    int grp = lane >> 3, lr = lane & 7;
    int row = row0 + lr + (grp & 1) * 8;
    int col = col0 + (grp >> 1) * 8;
    return base + (uint32_t)(row * 72 + col) * 2u;
}
// cluster-scope mbarrier wait (acquire.cluster)
__device__ __forceinline__ void mbar_waitc(uint32_t mbar, uint32_t parity){
    uint32_t done = 0;
    do {
        asm volatile("{\n\t.reg .pred p;\n\t"
            "mbarrier.try_wait.parity.acquire.cluster.shared::cta.b64 p, [%1], %2, 0x989680;\n\t"
            "selp.b32 %0, 1, 0, p;\n\t}"
            : "=r"(done) : "r"(mbar), "r"(parity) : "memory");
    } while(!done);
}

// ===================== Phase 1 (unchanged, verified round 6) =====================
#define P1_XH   0u
#define P1_XL   9216u
#define P1_W1H  18432u
#define P1_W1L  46080u
#define P1_W2H  73728u
#define P1_W2L  101376u
#define P1_BYTES 129024u

__global__ void __launch_bounds__(384,1) phase1_mma(
    const float* __restrict__ x, const float* __restrict__ Ww1,
    const float* __restrict__ Ww2, float* __restrict__ xg)
{
    extern __shared__ char sb[];
    const uint32_t s0 = smem_u32(sb);
    const int tid = threadIdx.x, wid = tid >> 5, lane = tid & 31;

    if (tid < 192){
        const int g = tid >> 6, row = tid & 63;
        float w[64];
        #pragma unroll
        for (int q = 0; q < 16; q++)
            ((float4*)w)[q] = ((const float4*)(Ww1 + tid * 64))[q];
        uint32_t eb = (uint32_t)(g * 4608 + row * 72);
        #pragma unroll
        for (int k = 0; k < 32; k++){
            uint2 hl = split2(w[2*k], w[2*k+1]);
            *(uint32_t*)(sb + P1_W1H + (eb + 2*k)*2) = hl.x;
            *(uint32_t*)(sb + P1_W1L + (eb + 2*k)*2) = hl.y;
        }
        #pragma unroll 4
        for (int b = 0; b < 64; b++) w[b] = Ww2[g * 4096 + b * 64 + row];
        #pragma unroll
        for (int k = 0; k < 32; k++){
            uint2 hl = split2(w[2*k], w[2*k+1]);
            *(uint32_t*)(sb + P1_W2H + (eb + 2*k)*2) = hl.x;
            *(uint32_t*)(sb + P1_W2L + (eb + 2*k)*2) = hl.y;
        }
    }

    const int g  = wid >> 2;
    const int rb = wid & 3;
    const uint32_t w1hB = s0 + P1_W1H + (uint32_t)g * 9216u;
    const uint32_t w1lB = s0 + P1_W1L + (uint32_t)g * 9216u;
    const uint32_t w2hB = s0 + P1_W2H + (uint32_t)g * 9216u;
    const uint32_t w2lB = s0 + P1_W2L + (uint32_t)g * 9216u;

    float4 xr[4];
    const int xi = tid >> 2, xj = (tid & 3) * 16;

    int p = blockIdx.x;
    if (p < NB*LS && tid < 256){
        const float4* s = (const float4*)(x + (size_t)p*4096 + xi*64 + xj);
        xr[0]=s[0]; xr[1]=s[1]; xr[2]=s[2]; xr[3]=s[3];
    }

    for (; p < NB*LS; p += gridDim.x){
        __syncthreads();
        if (tid < 256){
            const float* xf = (const float*)xr;
            uint32_t eb = (uint32_t)(xi * 72 + xj);
            #pragma unroll
            for (int k = 0; k < 8; k++){
                uint2 hl = split2(xf[2*k], xf[2*k+1]);
                *(uint32_t*)(sb + P1_XH + (eb + 2*k)*2) = hl.x;
                *(uint32_t*)(sb + P1_XL + (eb + 2*k)*2) = hl.y;
            }
        }
        __syncthreads();
        int pn = p + gridDim.x;
        if (pn < NB*LS && tid < 256){
            const float4* s = (const float4*)(x + (size_t)pn*4096 + xi*64 + xj);
            xr[0]=s[0]; xr[1]=s[1]; xr[2]=s[2]; xr[3]=s[3];
        }

        float D[8][4];
        #pragma unroll
        for (int t = 0; t < 8; t++){ D[t][0]=D[t][1]=D[t][2]=D[t][3]=0.0f; }
        #pragma unroll
        for (int kc = 0; kc < 4; kc++){
            uint32_t Ah[4], Al[4];
            ldm4(Ah, fraddr(w1hB, rb*16, kc*16, lane));
            ldm4(Al, fraddr(w1lB, rb*16, kc*16, lane));
            #pragma unroll
            for (int nb = 0; nb < 4; nb++){
                uint32_t Bh[4], Bl[4];
                ldm4t(Bh, fraddr(s0 + P1_XH, kc*16, nb*16, lane));
                ldm4t(Bl, fraddr(s0 + P1_XL, kc*16, nb*16, lane));
                mma16816(D[2*nb],   Ah, Bh[0], Bh[1]);
                mma16816(D[2*nb+1], Ah, Bh[2], Bh[3]);
                mma16816(D[2*nb],   Ah, Bl[0], Bl[1]);
                mma16816(D[2*nb+1], Ah, Bl[2], Bl[3]);
                mma16816(D[2*nb],   Al, Bh[0], Bh[1]);
                mma16816(D[2*nb+1], Al, Bh[2], Bh[3]);
            }
        }

        uint32_t A2h[4][4], A2l[4][4];
        #pragma unroll
        for (int kc = 0; kc < 4; kc++){
            uint2 p0 = split2(D[2*kc][0],   D[2*kc][1]);
            uint2 p1 = split2(D[2*kc][2],   D[2*kc][3]);
            uint2 p2 = split2(D[2*kc+1][0], D[2*kc+1][1]);
            uint2 p3 = split2(D[2*kc+1][2], D[2*kc+1][3]);
            A2h[kc][0]=p0.x; A2h[kc][1]=p1.x; A2h[kc][2]=p2.x; A2h[kc][3]=p3.x;
            A2l[kc][0]=p0.y; A2l[kc][1]=p1.y; A2l[kc][2]=p2.y; A2l[kc][3]=p3.y;
        }

        float E[8][4];
        #pragma unroll
        for (int t = 0; t < 8; t++){ E[t][0]=E[t][1]=E[t][2]=E[t][3]=0.0f; }
        #pragma unroll
        for (int kc = 0; kc < 4; kc++){
            #pragma unroll
            for (int nb = 0; nb < 4; nb++){
                uint32_t Bh[4], Bl[4];
                ldm4t(Bh, fraddr(w2hB, kc*16, nb*16, lane));
                ldm4t(Bl, fraddr(w2lB, kc*16, nb*16, lane));
                mma16816(E[2*nb],   A2h[kc], Bh[0], Bh[1]);
                mma16816(E[2*nb+1], A2h[kc], Bh[2], Bh[3]);
                mma16816(E[2*nb],   A2h[kc], Bl[0], Bl[1]);
                mma16816(E[2*nb+1], A2h[kc], Bl[2], Bl[3]);
                mma16816(E[2*nb],   A2l[kc], Bh[0], Bh[1]);
                mma16816(E[2*nb+1], A2l[kc], Bh[2], Bh[3]);
            }
        }

        {
            const int n = p >> 7, l = p & 127;
            float* dst = xg + ((size_t)((l*3+g)*NB + n))*4096;
            const int r0 = rb*16 + (lane >> 2);
            const int cb = (lane & 3) * 2;
            #pragma unroll
            for (int nb = 0; nb < 4; nb++){
                #pragma unroll
                for (int hf = 0; hf < 2; hf++){
                    int t = 2*nb + hf;
                    int b = nb*16 + hf*8 + cb;
                    float* q = dst + r0*64 + b;
                    *(float2*)q          = make_float2(E[t][0], E[t][1]);
                    *(float2*)(q + 8*64) = make_float2(E[t][2], E[t][3]);
                }
            }
        }
    }
}

// ===================== Phase 2 (mma.sync, cluster-2, full-bf16 recurrence) =====================
// HB0 0 (9216) | HB1 9216 | W2H 18432 (27648) | EP 46080 (52224) | XGS 98304 (52224) | MB 150528
#define S2_W2H 18432u
#define S2_EP  46080u
#define S2_XGS 98304u
#define S2_MB  150528u
#define S2_BYTES 150656u
#define EPS 68
#define EPP 2176
#define XGB 6528

__global__ void __launch_bounds__(384,1) __cluster_dims__(2,1,1) phase2_mma(
    const float* __restrict__ Wu1, const float* __restrict__ Wu2,
    const float* __restrict__ xg, float* __restrict__ out)
{
    extern __shared__ char sb[];
    const uint32_t s0 = smem_u32(sb);
    float* smf = (float*)sb;
    const int tid = threadIdx.x, wid = tid >> 5, lane = tid & 31;
    uint32_t rk; asm("mov.u32 %0, %%cluster_ctarank;" : "=r"(rk));
    const int n  = blockIdx.x >> 1;
    const int A0 = (int)rk * 32;
    const int EPf = 11520, XGSf = 24576;

    // ---- init: Wu2t single-bf16 ----
    if (tid < 192){
        const int g = tid >> 6, j = tid & 63;
        float w[64];
        #pragma unroll 4
        for (int b = 0; b < 64; b++) w[b] = Wu2[g*4096 + b*64 + j];
        uint32_t eb = (uint32_t)((g*64 + j) * 72);
        #pragma unroll
        for (int k = 0; k < 32; k++)
            *(uint32_t*)(sb + S2_W2H + (eb + 2*k)*2) = cvt2(w[2*k], w[2*k+1]);
    }
    // Wu1 own rows, single-bf16, into temp (XGS area)
    if (tid < 96){
        const int g = tid >> 5, a = tid & 31;
        float w[64];
        #pragma unroll
        for (int q = 0; q < 16; q++)
            ((float4*)w)[q] = ((const float4*)(Wu1 + (size_t)(g*64 + A0 + a)*64))[q];
        uint32_t eb = (uint32_t)((g*32 + a) * 72);
        #pragma unroll
        for (int k = 0; k < 32; k++)
            *(uint32_t*)(sb + S2_XGS + (eb + 2*k)*2) = cvt2(w[2*k], w[2*k+1]);
    }
    // zero both h buffers (2 x 9216 B)
    for (int i = tid; i < 4608; i += 384) ((uint32_t*)sb)[i] = 0;
    if (tid == 0)
        asm volatile("mbarrier.init.shared.b64 [%0], %1;" :: "r"(s0 + S2_MB), "r"(768u) : "memory");
    __syncthreads();

    const int g  = wid >> 2;
    const int rb = (wid >> 1) & 1;
    const int jh = wid & 1;
    uint32_t Ah[4][4];
    #pragma unroll
    for (int kc = 0; kc < 4; kc++)
        ldm4(Ah[kc], fraddr(s0 + S2_XGS + (uint32_t)g*4608u, rb*16, kc*16, lane));
    __syncthreads();

    const uint32_t w2hB = s0 + S2_W2H + (uint32_t)g * 9216u;

    float cst[2][4];
    #pragma unroll
    for (int cc = 0; cc < 2; cc++)
        #pragma unroll
        for (int k = 0; k < 4; k++) cst[cc][k] = 0.0f;

    uint32_t pb, pbar;
    asm("mapa.shared::cluster.u32 %0, %1, %2;" : "=r"(pb) : "r"(s0), "r"(rk^1u));
    asm("mapa.shared::cluster.u32 %0, %1, %2;" : "=r"(pbar) : "r"(s0 + S2_MB), "r"(rk^1u));

    #pragma unroll
    for (int k = 0; k < 4; k++){
        int idx = tid + 384*k;
        int gx = idx / 512, rem = idx & 511;
        int row = rem >> 4, off = rem & 15;
        cpa16(smf + XGSf + gx*EPP + row*EPS + off*4,
              xg + ((size_t)((0*3 + gx)*NB + n))*4096 + (A0+row)*64 + off*4);
    }
    asm volatile("cp.async.commit_group;");

    asm volatile("barrier.cluster.arrive.aligned;" ::: "memory");
    asm volatile("barrier.cluster.wait.aligned;" ::: "memory");

    int buf = 0, hb = 0;
    for (int t = 0; t < LS; t++){
        const uint32_t hsB = s0 + (uint32_t)hb*9216u;

        // ---- stage1 (all single-bf16; split accumulators) ----
        float Da[4][4], Db[4][4];
        #pragma unroll
        for (int q = 0; q < 4; q++){
            Da[q][0]=Da[q][1]=Da[q][2]=Da[q][3]=0.0f;
            Db[q][0]=Db[q][1]=Db[q][2]=Db[q][3]=0.0f;
        }
        #pragma unroll
        for (int kc = 0; kc < 4; kc++){
            float (*Dp)[4] = (kc < 2) ? Da : Db;
            #pragma unroll
            for (int nb = 0; nb < 2; nb++){
                uint32_t Bh[4];
                ldm4t(Bh, fraddr(hsB, kc*16, (jh*2+nb)*16, lane));
                mma16816(Dp[2*nb],   Ah[kc], Bh[0], Bh[1]);
                mma16816(Dp[2*nb+1], Ah[kc], Bh[2], Bh[3]);
            }
        }
        #pragma unroll
        for (int q = 0; q < 4; q++){
            Da[q][0]+=Db[q][0]; Da[q][1]+=Db[q][1];
            Da[q][2]+=Db[q][2]; Da[q][3]+=Db[q][3];
        }
        uint32_t A2h[2][4];
        #pragma unroll
        for (int c = 0; c < 2; c++){
            A2h[c][0] = cvt2(Da[2*c][0],   Da[2*c][1]);
            A2h[c][1] = cvt2(Da[2*c][2],   Da[2*c][3]);
            A2h[c][2] = cvt2(Da[2*c+1][0], Da[2*c+1][1]);
            A2h[c][3] = cvt2(Da[2*c+1][2], Da[2*c+1][3]);
        }
        // ---- stage2 partial (single-bf16) ----
        float E[8][4];
        #pragma unroll
        for (int q = 0; q < 8; q++){ E[q][0]=E[q][1]=E[q][2]=E[q][3]=0.0f; }
        #pragma unroll
        for (int c = 0; c < 2; c++){
            #pragma unroll
            for (int nb = 0; nb < 4; nb++){
                uint32_t Bh[4];
                ldm4t(Bh, fraddr(w2hB, jh*32 + c*16, nb*16, lane));
                mma16816(E[2*nb],   A2h[c], Bh[0], Bh[1]);
                mma16816(E[2*nb+1], A2h[c], Bh[2], Bh[3]);
            }
        }
        // ---- store E partial ----
        {
            float* dst = smf + EPf + (jh*3 + g)*EPP;
            const int r0 = rb*16 + (lane >> 2);
            const int cb = (lane & 3) * 2;
            #pragma unroll
            for (int nb = 0; nb < 4; nb++){
                #pragma unroll
                for (int hf = 0; hf < 2; hf++){
                    int q = 2*nb + hf;
                    int b = nb*16 + hf*8 + cb;
                    float* d2 = dst + r0*EPS + b;
                    *(float2*)d2            = make_float2(E[q][0], E[q][1]);
                    *(float2*)(d2 + 8*EPS)  = make_float2(E[q][2], E[q][3]);
                }
            }
        }
        asm volatile("cp.async.wait_group 0;");
        __syncthreads();                  // E + xg[t] visible

        // ---- epilogue: all 384 threads, chunk remap; h -> single bf16 ----
        float hv[2][4];
        const uint32_t hwb = (uint32_t)(hb^1)*9216u;
        #pragma unroll
        for (int cc = 0; cc < 2; cc++){
            int ch = tid + cc*384;
            if (ch < 512){
                int row = ch >> 4, c4 = (ch & 15) * 4;
                int be = row*EPS + c4;
                const float* ep = smf + EPf;
                const float* xb = smf + XGSf + buf*XGB;
                float4 z1 = *(const float4*)(ep + be);
                float4 z2 = *(const float4*)(ep + 3*EPP + be);
                float4 z3 = *(const float4*)(xb + be);
                float4 r1 = *(const float4*)(ep + 1*EPP + be);
                float4 r2 = *(const float4*)(ep + 4*EPP + be);
                float4 r3 = *(const float4*)(xb + 1*EPP + be);
                float4 o1 = *(const float4*)(ep + 2*EPP + be);
                float4 o2 = *(const float4*)(ep + 5*EPP + be);
                float4 o3 = *(const float4*)(xb + 2*EPP + be);
                float zs[4] = {z1.x+z2.x+z3.x, z1.y+z2.y+z3.y, z1.z+z2.z+z3.z, z1.w+z2.w+z3.w};
                float rs[4] = {r1.x+r2.x+r3.x, r1.y+r2.y+r3.y, r1.z+r2.z+r3.z, r1.w+r2.w+r3.w};
                float os[4] = {o1.x+o2.x+o3.x, o1.y+o2.y+o3.y, o1.z+o2.z+o3.z, o1.w+o2.w+o3.w};
                #pragma unroll
                for (int k = 0; k < 4; k++){
                    float z = sigm(zs[k]);
                    float r = sigm(rs[k]);
                    float o = sigm(os[k]);
                    cst[cc][k] = r * (cst[cc][k] + z);
                    hv[cc][k] = o * sigm(cst[cc][k]);
                }
                uint32_t u01 = cvt2(hv[cc][0], hv[cc][1]);
                uint32_t u23 = cvt2(hv[cc][2], hv[cc][3]);
                uint64_t hpk;
                asm("mov.b64 %0, {%1,%2};" : "=l"(hpk) : "r"(u01), "r"(u23));
                const uint32_t ho = (uint32_t)(((A0 + row)*72 + c4) * 2);
                *(uint64_t*)(sb + hwb + ho) = hpk;
                asm volatile("st.shared::cluster.b64 [%0], %1;" :: "r"(pb + hwb + ho), "l"(hpk));
            }
        }
        asm volatile("mbarrier.arrive.release.cluster.shared::cluster.b64 _, [%0];"
                     :: "r"(s0 + S2_MB) : "memory");
        asm volatile("mbarrier.arrive.release.cluster.shared::cluster.b64 _, [%0];"
                     :: "r"(pbar) : "memory");

        // overlap: output STG + next xg prefetch before waiting
        #pragma unroll
        for (int cc = 0; cc < 2; cc++){
            int ch = tid + cc*384;
            if (ch < 512){
                int row = ch >> 4, c4 = (ch & 15) * 4;
                float* od2 = out + ((size_t)(n*LS + t))*4096 + (A0 + row)*64 + c4;
                *(float4*)od2 = make_float4(hv[cc][0],hv[cc][1],hv[cc][2],hv[cc][3]);
                if (t == LS-1){
                    float* hl2 = out + (size_t)NB*LS*4096 + (size_t)n*4096 + (A0 + row)*64 + c4;
                    *(float4*)hl2 = make_float4(hv[cc][0],hv[cc][1],hv[cc][2],hv[cc][3]);
                }
            }
        }
        if (t + 1 < LS){
            #pragma unroll
            for (int k = 0; k < 4; k++){
                int idx = tid + 384*k;
                int gx = idx / 512, rem = idx & 511;
                int row = rem >> 4, off = rem & 15;
                cpa16(smf + XGSf + (buf^1)*XGB + gx*EPP + row*EPS + off*4,
                      xg + ((size_t)(((t+1)*3 + gx)*NB + n))*4096 + (A0+row)*64 + off*4);
            }
        }
        asm volatile("cp.async.commit_group;");

        mbar_waitc(s0 + S2_MB, (uint32_t)(t & 1));
        buf ^= 1; hb ^= 1;
    }

    // c_last
    #pragma unroll
    for (int cc = 0; cc < 2; cc++){
        int ch = tid + cc*384;
        if (ch < 512){
            int row = ch >> 4, c4 = (ch & 15) * 4;
            float* cl = out + (size_t)NB*LS*4096 + (size_t)NB*4096
                            + (size_t)n*4096 + (A0 + row)*64 + c4;
            *(float4*)cl = make_float4(cst[cc][0],cst[cc][1],cst[cc][2],cst[cc][3]);
        }
    }
    asm volatile("barrier.cluster.arrive.aligned;" ::: "memory");
    asm volatile("barrier.cluster.wait.aligned;" ::: "memory");
}

// ---------------------------------------------------------------------------
extern "C" void kernel_launch(void* const* d_in, const int* in_sizes, int n_in,
                              void* d_out, int out_size)
{
    const float* x   = (const float*)d_in[0];
    const float* Ww1 = (const float*)d_in[1];
    const float* Ww2 = (const float*)d_in[2];
    const float* Wu1 = (const float*)d_in[3];
    const float* Wu2 = (const float*)d_in[4];
    float* out = (float*)d_out;

    float* xg = nullptr;
    cudaGetSymbolAddress((void**)&xg, g_xg);

    cudaFuncSetAttribute(phase1_mma, cudaFuncAttributeMaxDynamicSharedMemorySize, (int)P1_BYTES);
    cudaFuncSetAttribute(phase2_mma, cudaFuncAttributeMaxDynamicSharedMemorySize, (int)S2_BYTES);

    phase1_mma<<<148, 384, P1_BYTES>>>(x, Ww1, Ww2, xg);
    phase2_mma<<<2 * NB, 384, S2_BYTES>>>(Wu1, Wu2, xg, out);
}

// round 16
// speedup vs baseline: 1.4546x; 1.1399x over previous
#include <cuda_runtime.h>
#include <cuda_bf16.h>
#include <cstdint>
#include <cstddef>

#define NB 64
#define LS 128

__device__ float g_xg[(size_t)LS*3*NB*4096];

__device__ __forceinline__ float sigm(float x){ return 1.0f/(1.0f+__expf(-x)); }
__device__ __forceinline__ void cpa16(void* dst, const float* src){
    asm volatile("cp.async.ca.shared.global [%0], [%1], 16;"
                 :: "r"((uint32_t)__cvta_generic_to_shared(dst)), "l"(src)); }
__device__ __forceinline__ uint32_t smem_u32(const void* p){
    uint32_t a; asm("{ .reg .u64 t; cvta.to.shared.u64 t, %1; cvt.u32.u64 %0, t; }"
                    : "=r"(a) : "l"(p)); return a; }

__device__ __forceinline__ uint32_t cvt2(float f0, float f1){
    __nv_bfloat162 h2 = __floats2bfloat162_rn(f0, f1);
    return *(uint32_t*)&h2;
}
__device__ __forceinline__ void ldm4(uint32_t* r, uint32_t addr){
    asm volatile("ldmatrix.sync.aligned.m8n8.x4.shared.b16 {%0,%1,%2,%3}, [%4];"
        : "=r"(r[0]),"=r"(r[1]),"=r"(r[2]),"=r"(r[3]) : "r"(addr));
}
__device__ __forceinline__ void ldm4t(uint32_t* r, uint32_t addr){
    asm volatile("ldmatrix.sync.aligned.m8n8.x4.trans.shared.b16 {%0,%1,%2,%3}, [%4];"
        : "=r"(r[0]),"=r"(r[1]),"=r"(r[2]),"=r"(r[3]) : "r"(addr));
}
__device__ __forceinline__ void mma16816(float* d, const uint32_t* a, uint32_t b0, uint32_t b1){
    asm volatile("mma.sync.aligned.m16n8k16.row.col.f32.bf16.bf16.f32 "
        "{%0,%1,%2,%3}, {%4,%5,%6,%7}, {%8,%9}, {%0,%1,%2,%3};"
        : "+f"(d[0]),"+f"(d[1]),"+f"(d[2]),"+f"(d[3])
        : "r"(a[0]),"r"(a[1]),"r"(a[2]),"r"(a[3]), "r"(b0),"r"(b1));
}
// lane address into 16x16 block of row-major bf16 array, row stride 72 elems
__device__ __forceinline__ uint32_t fraddr(uint32_t base, int row0, int col0, int lane){
    int grp = lane >> 3, lr = lane & 7;
    int row = row0 + lr + (grp & 1) * 8;
    int col = col0 + (grp >> 1) * 8;
    return base + (uint32_t)(row * 72 + col) * 2u;
}
// cluster-scope mbarrier wait (acquire.cluster)
__device__ __forceinline__ void mbar_waitc(uint32_t mbar, uint32_t parity){
    uint32_t done = 0;
    do {
        asm volatile("{\n\t.reg .pred p;\n\t"
            "mbarrier.try_wait.parity.acquire.cluster.shared::cta.b64 p, [%1], %2, 0x989680;\n\t"
            "selp.b32 %0, 1, 0, p;\n\t}"
            : "=r"(done) : "r"(mbar), "r"(parity) : "memory");
    } while(!done);
}

// ===================== Phase 1 (single-bf16) =====================
// XH 0 (9216) | W1H 9216 (27648) | W2H 36864 (27648)
#define P1_XH   0u
#define P1_W1H  9216u
#define P1_W2H  36864u
#define P1_BYTES 64512u

__global__ void __launch_bounds__(384,1) phase1_mma(
    const float* __restrict__ x, const float* __restrict__ Ww1,
    const float* __restrict__ Ww2, float* __restrict__ xg)
{
    extern __shared__ char sb[];
    const uint32_t s0 = smem_u32(sb);
    const int tid = threadIdx.x, wid = tid >> 5, lane = tid & 31;

    if (tid < 192){
        const int g = tid >> 6, row = tid & 63;
        float w[64];
        #pragma unroll
        for (int q = 0; q < 16; q++)
            ((float4*)w)[q] = ((const float4*)(Ww1 + tid * 64))[q];
        uint32_t eb = (uint32_t)(g * 4608 + row * 72);
        #pragma unroll
        for (int k = 0; k < 32; k++)
            *(uint32_t*)(sb + P1_W1H + (eb + 2*k)*2) = cvt2(w[2*k], w[2*k+1]);
        #pragma unroll 4
        for (int b = 0; b < 64; b++) w[b] = Ww2[g * 4096 + b * 64 + row];
        #pragma unroll
        for (int k = 0; k < 32; k++)
            *(uint32_t*)(sb + P1_W2H + (eb + 2*k)*2) = cvt2(w[2*k], w[2*k+1]);
    }

    const int g  = wid >> 2;
    const int rb = wid & 3;
    const uint32_t w1hB = s0 + P1_W1H + (uint32_t)g * 9216u;
    const uint32_t w2hB = s0 + P1_W2H + (uint32_t)g * 9216u;

    float4 xr[4];
    const int xi = tid >> 2, xj = (tid & 3) * 16;

    int p = blockIdx.x;
    if (p < NB*LS && tid < 256){
        const float4* s = (const float4*)(x + (size_t)p*4096 + xi*64 + xj);
        xr[0]=s[0]; xr[1]=s[1]; xr[2]=s[2]; xr[3]=s[3];
    }

    for (; p < NB*LS; p += gridDim.x){
        __syncthreads();
        if (tid < 256){
            const float* xf = (const float*)xr;
            uint32_t eb = (uint32_t)(xi * 72 + xj);
            #pragma unroll
            for (int k = 0; k < 8; k++)
                *(uint32_t*)(sb + P1_XH + (eb + 2*k)*2) = cvt2(xf[2*k], xf[2*k+1]);
        }
        __syncthreads();
        int pn = p + gridDim.x;
        if (pn < NB*LS && tid < 256){
            const float4* s = (const float4*)(x + (size_t)pn*4096 + xi*64 + xj);
            xr[0]=s[0]; xr[1]=s[1]; xr[2]=s[2]; xr[3]=s[3];
        }

        // stage1: D = Ww1[g, rb16 rows] @ X  (single-bf16)
        float D[8][4];
        #pragma unroll
        for (int t = 0; t < 8; t++){ D[t][0]=D[t][1]=D[t][2]=D[t][3]=0.0f; }
        #pragma unroll
        for (int kc = 0; kc < 4; kc++){
            uint32_t Ah[4];
            ldm4(Ah, fraddr(w1hB, rb*16, kc*16, lane));
            #pragma unroll
            for (int nb = 0; nb < 4; nb++){
                uint32_t Bh[4];
                ldm4t(Bh, fraddr(s0 + P1_XH, kc*16, nb*16, lane));
                mma16816(D[2*nb],   Ah, Bh[0], Bh[1]);
                mma16816(D[2*nb+1], Ah, Bh[2], Bh[3]);
            }
        }

        // repack D -> A2 (single-bf16)
        uint32_t A2h[4][4];
        #pragma unroll
        for (int kc = 0; kc < 4; kc++){
            A2h[kc][0] = cvt2(D[2*kc][0],   D[2*kc][1]);
            A2h[kc][1] = cvt2(D[2*kc][2],   D[2*kc][3]);
            A2h[kc][2] = cvt2(D[2*kc+1][0], D[2*kc+1][1]);
            A2h[kc][3] = cvt2(D[2*kc+1][2], D[2*kc+1][3]);
        }

        // stage2: E = T @ Ww2t[g]
        float E[8][4];
        #pragma unroll
        for (int t = 0; t < 8; t++){ E[t][0]=E[t][1]=E[t][2]=E[t][3]=0.0f; }
        #pragma unroll
        for (int kc = 0; kc < 4; kc++){
            #pragma unroll
            for (int nb = 0; nb < 4; nb++){
                uint32_t Bh[4];
                ldm4t(Bh, fraddr(w2hB, kc*16, nb*16, lane));
                mma16816(E[2*nb],   A2h[kc], Bh[0], Bh[1]);
                mma16816(E[2*nb+1], A2h[kc], Bh[2], Bh[3]);
            }
        }

        {
            const int n = p >> 7, l = p & 127;
            float* dst = xg + ((size_t)((l*3+g)*NB + n))*4096;
            const int r0 = rb*16 + (lane >> 2);
            const int cb = (lane & 3) * 2;
            #pragma unroll
            for (int nb = 0; nb < 4; nb++){
                #pragma unroll
                for (int hf = 0; hf < 2; hf++){
                    int t = 2*nb + hf;
                    int b = nb*16 + hf*8 + cb;
                    float* q = dst + r0*64 + b;
                    *(float2*)q          = make_float2(E[t][0], E[t][1]);
                    *(float2*)(q + 8*64) = make_float2(E[t][2], E[t][3]);
                }
            }
        }
    }
}

// ===================== Phase 2 (unchanged from round 15) =====================
#define S2_W2H 18432u
#define S2_EP  46080u
#define S2_XGS 98304u
#define S2_MB  150528u
#define S2_BYTES 150656u
#define EPS 68
#define EPP 2176
#define XGB 6528

__global__ void __launch_bounds__(384,1) __cluster_dims__(2,1,1) phase2_mma(
    const float* __restrict__ Wu1, const float* __restrict__ Wu2,
    const float* __restrict__ xg, float* __restrict__ out)
{
    extern __shared__ char sb[];
    const uint32_t s0 = smem_u32(sb);
    float* smf = (float*)sb;
    const int tid = threadIdx.x, wid = tid >> 5, lane = tid & 31;
    uint32_t rk; asm("mov.u32 %0, %%cluster_ctarank;" : "=r"(rk));
    const int n  = blockIdx.x >> 1;
    const int A0 = (int)rk * 32;
    const int EPf = 11520, XGSf = 24576;

    if (tid < 192){
        const int g = tid >> 6, j = tid & 63;
        float w[64];
        #pragma unroll 4
        for (int b = 0; b < 64; b++) w[b] = Wu2[g*4096 + b*64 + j];
        uint32_t eb = (uint32_t)((g*64 + j) * 72);
        #pragma unroll
        for (int k = 0; k < 32; k++)
            *(uint32_t*)(sb + S2_W2H + (eb + 2*k)*2) = cvt2(w[2*k], w[2*k+1]);
    }
    if (tid < 96){
        const int g = tid >> 5, a = tid & 31;
        float w[64];
        #pragma unroll
        for (int q = 0; q < 16; q++)
            ((float4*)w)[q] = ((const float4*)(Wu1 + (size_t)(g*64 + A0 + a)*64))[q];
        uint32_t eb = (uint32_t)((g*32 + a) * 72);
        #pragma unroll
        for (int k = 0; k < 32; k++)
            *(uint32_t*)(sb + S2_XGS + (eb + 2*k)*2) = cvt2(w[2*k], w[2*k+1]);
    }
    for (int i = tid; i < 4608; i += 384) ((uint32_t*)sb)[i] = 0;
    if (tid == 0)
        asm volatile("mbarrier.init.shared.b64 [%0], %1;" :: "r"(s0 + S2_MB), "r"(768u) : "memory");
    __syncthreads();

    const int g  = wid >> 2;
    const int rb = (wid >> 1) & 1;
    const int jh = wid & 1;
    uint32_t Ah[4][4];
    #pragma unroll
    for (int kc = 0; kc < 4; kc++)
        ldm4(Ah[kc], fraddr(s0 + S2_XGS + (uint32_t)g*4608u, rb*16, kc*16, lane));
    __syncthreads();

    const uint32_t w2hB = s0 + S2_W2H + (uint32_t)g * 9216u;

    float cst[2][4];
    #pragma unroll
    for (int cc = 0; cc < 2; cc++)
        #pragma unroll
        for (int k = 0; k < 4; k++) cst[cc][k] = 0.0f;

    uint32_t pb, pbar;
    asm("mapa.shared::cluster.u32 %0, %1, %2;" : "=r"(pb) : "r"(s0), "r"(rk^1u));
    asm("mapa.shared::cluster.u32 %0, %1, %2;" : "=r"(pbar) : "r"(s0 + S2_MB), "r"(rk^1u));

    #pragma unroll
    for (int k = 0; k < 4; k++){
        int idx = tid + 384*k;
        int gx = idx / 512, rem = idx & 511;
        int row = rem >> 4, off = rem & 15;
        cpa16(smf + XGSf + gx*EPP + row*EPS + off*4,
              xg + ((size_t)((0*3 + gx)*NB + n))*4096 + (A0+row)*64 + off*4);
    }
    asm volatile("cp.async.commit_group;");

    asm volatile("barrier.cluster.arrive.aligned;" ::: "memory");
    asm volatile("barrier.cluster.wait.aligned;" ::: "memory");

    int buf = 0, hb = 0;
    for (int t = 0; t < LS; t++){
        const uint32_t hsB = s0 + (uint32_t)hb*9216u;

        float Da[4][4], Db[4][4];
        #pragma unroll
        for (int q = 0; q < 4; q++){
            Da[q][0]=Da[q][1]=Da[q][2]=Da[q][3]=0.0f;
            Db[q][0]=Db[q][1]=Db[q][2]=Db[q][3]=0.0f;
        }
        #pragma unroll
        for (int kc = 0; kc < 4; kc++){
            float (*Dp)[4] = (kc < 2) ? Da : Db;
            #pragma unroll
            for (int nb = 0; nb < 2; nb++){
                uint32_t Bh[4];
                ldm4t(Bh, fraddr(hsB, kc*16, (jh*2+nb)*16, lane));
                mma16816(Dp[2*nb],   Ah[kc], Bh[0], Bh[1]);
                mma16816(Dp[2*nb+1], Ah[kc], Bh[2], Bh[3]);
            }
        }
        #pragma unroll
        for (int q = 0; q < 4; q++){
            Da[q][0]+=Db[q][0]; Da[q][1]+=Db[q][1];
            Da[q][2]+=Db[q][2]; Da[q][3]+=Db[q][3];
        }
        uint32_t A2h[2][4];
        #pragma unroll
        for (int c = 0; c < 2; c++){
            A2h[c][0] = cvt2(Da[2*c][0],   Da[2*c][1]);
            A2h[c][1] = cvt2(Da[2*c][2],   Da[2*c][3]);
            A2h[c][2] = cvt2(Da[2*c+1][0], Da[2*c+1][1]);
            A2h[c][3] = cvt2(Da[2*c+1][2], Da[2*c+1][3]);
        }
        float E[8][4];
        #pragma unroll
        for (int q = 0; q < 8; q++){ E[q][0]=E[q][1]=E[q][2]=E[q][3]=0.0f; }
        #pragma unroll
        for (int c = 0; c < 2; c++){
            #pragma unroll
            for (int nb = 0; nb < 4; nb++){
                uint32_t Bh[4];
                ldm4t(Bh, fraddr(w2hB, jh*32 + c*16, nb*16, lane));
                mma16816(E[2*nb],   A2h[c], Bh[0], Bh[1]);
                mma16816(E[2*nb+1], A2h[c], Bh[2], Bh[3]);
            }
        }
        {
            float* dst = smf + EPf + (jh*3 + g)*EPP;
            const int r0 = rb*16 + (lane >> 2);
            const int cb = (lane & 3) * 2;
            #pragma unroll
            for (int nb = 0; nb < 4; nb++){
                #pragma unroll
                for (int hf = 0; hf < 2; hf++){
                    int q = 2*nb + hf;
                    int b = nb*16 + hf*8 + cb;
                    float* d2 = dst + r0*EPS + b;
                    *(float2*)d2            = make_float2(E[q][0], E[q][1]);
                    *(float2*)(d2 + 8*EPS)  = make_float2(E[q][2], E[q][3]);
                }
            }
        }
        asm volatile("cp.async.wait_group 0;");
        __syncthreads();

        float hv[2][4];
        const uint32_t hwb = (uint32_t)(hb^1)*9216u;
        #pragma unroll
        for (int cc = 0; cc < 2; cc++){
            int ch = tid + cc*384;
            if (ch < 512){
                int row = ch >> 4, c4 = (ch & 15) * 4;
                int be = row*EPS + c4;
                const float* ep = smf + EPf;
                const float* xb = smf + XGSf + buf*XGB;
                float4 z1 = *(const float4*)(ep + be);
                float4 z2 = *(const float4*)(ep + 3*EPP + be);
                float4 z3 = *(const float4*)(xb + be);
                float4 r1 = *(const float4*)(ep + 1*EPP + be);
                float4 r2 = *(const float4*)(ep + 4*EPP + be);
                float4 r3 = *(const float4*)(xb + 1*EPP + be);
                float4 o1 = *(const float4*)(ep + 2*EPP + be);
                float4 o2 = *(const float4*)(ep + 5*EPP + be);
                float4 o3 = *(const float4*)(xb + 2*EPP + be);
                float zs[4] = {z1.x+z2.x+z3.x, z1.y+z2.y+z3.y, z1.z+z2.z+z3.z, z1.w+z2.w+z3.w};
                float rs[4] = {r1.x+r2.x+r3.x, r1.y+r2.y+r3.y, r1.z+r2.z+r3.z, r1.w+r2.w+r3.w};
                float os[4] = {o1.x+o2.x+o3.x, o1.y+o2.y+o3.y, o1.z+o2.z+o3.z, o1.w+o2.w+o3.w};
                #pragma unroll
                for (int k = 0; k < 4; k++){
                    float z = sigm(zs[k]);
                    float r = sigm(rs[k]);
                    float o = sigm(os[k]);
                    cst[cc][k] = r * (cst[cc][k] + z);
                    hv[cc][k] = o * sigm(cst[cc][k]);
                }
                uint32_t u01 = cvt2(hv[cc][0], hv[cc][1]);
                uint32_t u23 = cvt2(hv[cc][2], hv[cc][3]);
                uint64_t hpk;
                asm("mov.b64 %0, {%1,%2};" : "=l"(hpk) : "r"(u01), "r"(u23));
                const uint32_t ho = (uint32_t)(((A0 + row)*72 + c4) * 2);
                *(uint64_t*)(sb + hwb + ho) = hpk;
                asm volatile("st.shared::cluster.b64 [%0], %1;" :: "r"(pb + hwb + ho), "l"(hpk));
            }
        }
        asm volatile("mbarrier.arrive.release.cluster.shared::cluster.b64 _, [%0];"
                     :: "r"(s0 + S2_MB) : "memory");
        asm volatile("mbarrier.arrive.release.cluster.shared::cluster.b64 _, [%0];"
                     :: "r"(pbar) : "memory");

        #pragma unroll
        for (int cc = 0; cc < 2; cc++){
            int ch = tid + cc*384;
            if (ch < 512){
                int row = ch >> 4, c4 = (ch & 15) * 4;
                float* od2 = out + ((size_t)(n*LS + t))*4096 + (A0 + row)*64 + c4;
                *(float4*)od2 = make_float4(hv[cc][0],hv[cc][1],hv[cc][2],hv[cc][3]);
                if (t == LS-1){
                    float* hl2 = out + (size_t)NB*LS*4096 + (size_t)n*4096 + (A0 + row)*64 + c4;
                    *(float4*)hl2 = make_float4(hv[cc][0],hv[cc][1],hv[cc][2],hv[cc][3]);
                }
            }
        }
        if (t + 1 < LS){
            #pragma unroll
            for (int k = 0; k < 4; k++){
                int idx = tid + 384*k;
                int gx = idx / 512, rem = idx & 511;
                int row = rem >> 4, off = rem & 15;
                cpa16(smf + XGSf + (buf^1)*XGB + gx*EPP + row*EPS + off*4,
                      xg + ((size_t)(((t+1)*3 + gx)*NB + n))*4096 + (A0+row)*64 + off*4);
            }
        }
        asm volatile("cp.async.commit_group;");

        mbar_waitc(s0 + S2_MB, (uint32_t)(t & 1));
        buf ^= 1; hb ^= 1;
    }

    #pragma unroll
    for (int cc = 0; cc < 2; cc++){
        int ch = tid + cc*384;
        if (ch < 512){
            int row = ch >> 4, c4 = (ch & 15) * 4;
            float* cl = out + (size_t)NB*LS*4096 + (size_t)NB*4096
                            + (size_t)n*4096 + (A0 + row)*64 + c4;
            *(float4*)cl = make_float4(cst[cc][0],cst[cc][1],cst[cc][2],cst[cc][3]);
        }
    }
    asm volatile("barrier.cluster.arrive.aligned;" ::: "memory");
    asm volatile("barrier.cluster.wait.aligned;" ::: "memory");
}

// ---------------------------------------------------------------------------
extern "C" void kernel_launch(void* const* d_in, const int* in_sizes, int n_in,
                              void* d_out, int out_size)
{
    const float* x   = (const float*)d_in[0];
    const float* Ww1 = (const float*)d_in[1];
    const float* Ww2 = (const float*)d_in[2];
    const float* Wu1 = (const float*)d_in[3];
    const float* Wu2 = (const float*)d_in[4];
    float* out = (float*)d_out;

    float* xg = nullptr;
    cudaGetSymbolAddress((void**)&xg, g_xg);

    cudaFuncSetAttribute(phase1_mma, cudaFuncAttributeMaxDynamicSharedMemorySize, (int)P1_BYTES);
    cudaFuncSetAttribute(phase2_mma, cudaFuncAttributeMaxDynamicSharedMemorySize, (int)S2_BYTES);

    phase1_mma<<<148, 384, P1_BYTES>>>(x, Ww1, Ww2, xg);
    phase2_mma<<<2 * NB, 384, S2_BYTES>>>(Wu1, Wu2, xg, out);
}

// round 17
// speedup vs baseline: 1.4742x; 1.0135x over previous
#include <cuda_runtime.h>
#include <cuda_bf16.h>
#include <cstdint>
#include <cstddef>

#define NB 64
#define LS 128

__device__ float g_xg[(size_t)LS*3*NB*4096];

__device__ __forceinline__ float sigm(float x){ return 1.0f/(1.0f+__expf(-x)); }
__device__ __forceinline__ void cpa16(void* dst, const float* src){
    asm volatile("cp.async.ca.shared.global [%0], [%1], 16;"
                 :: "r"((uint32_t)__cvta_generic_to_shared(dst)), "l"(src)); }
__device__ __forceinline__ uint32_t smem_u32(const void* p){
    uint32_t a; asm("{ .reg .u64 t; cvta.to.shared.u64 t, %1; cvt.u32.u64 %0, t; }"
                    : "=r"(a) : "l"(p)); return a; }

__device__ __forceinline__ uint32_t cvt2(float f0, float f1){
    __nv_bfloat162 h2 = __floats2bfloat162_rn(f0, f1);
    return *(uint32_t*)&h2;
}
__device__ __forceinline__ void ldm4(uint32_t* r, uint32_t addr){
    asm volatile("ldmatrix.sync.aligned.m8n8.x4.shared.b16 {%0,%1,%2,%3}, [%4];"
        : "=r"(r[0]),"=r"(r[1]),"=r"(r[2]),"=r"(r[3]) : "r"(addr));
}
__device__ __forceinline__ void ldm4t(uint32_t* r, uint32_t addr){
    asm volatile("ldmatrix.sync.aligned.m8n8.x4.trans.shared.b16 {%0,%1,%2,%3}, [%4];"
        : "=r"(r[0]),"=r"(r[1]),"=r"(r[2]),"=r"(r[3]) : "r"(addr));
}
__device__ __forceinline__ void mma16816(float* d, const uint32_t* a, uint32_t b0, uint32_t b1){
    asm volatile("mma.sync.aligned.m16n8k16.row.col.f32.bf16.bf16.f32 "
        "{%0,%1,%2,%3}, {%4,%5,%6,%7}, {%8,%9}, {%0,%1,%2,%3};"
        : "+f"(d[0]),"+f"(d[1]),"+f"(d[2]),"+f"(d[3])
        : "r"(a[0]),"r"(a[1]),"r"(a[2]),"r"(a[3]), "r"(b0),"r"(b1));
}
// lane address into 16x16 block of row-major bf16 array, row stride 72 elems
__device__ __forceinline__ uint32_t fraddr(uint32_t base, int row0, int col0, int lane){
    int grp = lane >> 3, lr = lane & 7;
    int row = row0 + lr + (grp & 1) * 8;
    int col = col0 + (grp >> 1) * 8;
    return base + (uint32_t)(row * 72 + col) * 2u;
}
// cluster-scope mbarrier wait (acquire.cluster)
__device__ __forceinline__ void mbar_waitc(uint32_t mbar, uint32_t parity){
    uint32_t done = 0;
    do {
        asm volatile("{\n\t.reg .pred p;\n\t"
            "mbarrier.try_wait.parity.acquire.cluster.shared::cta.b64 p, [%1], %2, 0x989680;\n\t"
            "selp.b32 %0, 1, 0, p;\n\t}"
            : "=r"(done) : "r"(mbar), "r"(parity) : "memory");
    } while(!done);
}

// ===================== Phase 1 (single-bf16, unchanged from round 16) =====================
#define P1_XH   0u
#define P1_W1H  9216u
#define P1_W2H  36864u
#define P1_BYTES 64512u

__global__ void __launch_bounds__(384,1) phase1_mma(
    const float* __restrict__ x, const float* __restrict__ Ww1,
    const float* __restrict__ Ww2, float* __restrict__ xg)
{
    extern __shared__ char sb[];
    const uint32_t s0 = smem_u32(sb);
    const int tid = threadIdx.x, wid = tid >> 5, lane = tid & 31;

    if (tid < 192){
        const int g = tid >> 6, row = tid & 63;
        float w[64];
        #pragma unroll
        for (int q = 0; q < 16; q++)
            ((float4*)w)[q] = ((const float4*)(Ww1 + tid * 64))[q];
        uint32_t eb = (uint32_t)(g * 4608 + row * 72);
        #pragma unroll
        for (int k = 0; k < 32; k++)
            *(uint32_t*)(sb + P1_W1H + (eb + 2*k)*2) = cvt2(w[2*k], w[2*k+1]);
        #pragma unroll 4
        for (int b = 0; b < 64; b++) w[b] = Ww2[g * 4096 + b * 64 + row];
        #pragma unroll
        for (int k = 0; k < 32; k++)
            *(uint32_t*)(sb + P1_W2H + (eb + 2*k)*2) = cvt2(w[2*k], w[2*k+1]);
    }

    const int g  = wid >> 2;
    const int rb = wid & 3;
    const uint32_t w1hB = s0 + P1_W1H + (uint32_t)g * 9216u;
    const uint32_t w2hB = s0 + P1_W2H + (uint32_t)g * 9216u;

    float4 xr[4];
    const int xi = tid >> 2, xj = (tid & 3) * 16;

    int p = blockIdx.x;
    if (p < NB*LS && tid < 256){
        const float4* s = (const float4*)(x + (size_t)p*4096 + xi*64 + xj);
        xr[0]=s[0]; xr[1]=s[1]; xr[2]=s[2]; xr[3]=s[3];
    }

    for (; p < NB*LS; p += gridDim.x){
        __syncthreads();
        if (tid < 256){
            const float* xf = (const float*)xr;
            uint32_t eb = (uint32_t)(xi * 72 + xj);
            #pragma unroll
            for (int k = 0; k < 8; k++)
                *(uint32_t*)(sb + P1_XH + (eb + 2*k)*2) = cvt2(xf[2*k], xf[2*k+1]);
        }
        __syncthreads();
        int pn = p + gridDim.x;
        if (pn < NB*LS && tid < 256){
            const float4* s = (const float4*)(x + (size_t)pn*4096 + xi*64 + xj);
            xr[0]=s[0]; xr[1]=s[1]; xr[2]=s[2]; xr[3]=s[3];
        }

        float D[8][4];
        #pragma unroll
        for (int t = 0; t < 8; t++){ D[t][0]=D[t][1]=D[t][2]=D[t][3]=0.0f; }
        #pragma unroll
        for (int kc = 0; kc < 4; kc++){
            uint32_t Ah[4];
            ldm4(Ah, fraddr(w1hB, rb*16, kc*16, lane));
            #pragma unroll
            for (int nb = 0; nb < 4; nb++){
                uint32_t Bh[4];
                ldm4t(Bh, fraddr(s0 + P1_XH, kc*16, nb*16, lane));
                mma16816(D[2*nb],   Ah, Bh[0], Bh[1]);
                mma16816(D[2*nb+1], Ah, Bh[2], Bh[3]);
            }
        }

        uint32_t A2h[4][4];
        #pragma unroll
        for (int kc = 0; kc < 4; kc++){
            A2h[kc][0] = cvt2(D[2*kc][0],   D[2*kc][1]);
            A2h[kc][1] = cvt2(D[2*kc][2],   D[2*kc][3]);
            A2h[kc][2] = cvt2(D[2*kc+1][0], D[2*kc+1][1]);
            A2h[kc][3] = cvt2(D[2*kc+1][2], D[2*kc+1][3]);
        }

        float E[8][4];
        #pragma unroll
        for (int t = 0; t < 8; t++){ E[t][0]=E[t][1]=E[t][2]=E[t][3]=0.0f; }
        #pragma unroll
        for (int kc = 0; kc < 4; kc++){
            #pragma unroll
            for (int nb = 0; nb < 4; nb++){
                uint32_t Bh[4];
                ldm4t(Bh, fraddr(w2hB, kc*16, nb*16, lane));
                mma16816(E[2*nb],   A2h[kc], Bh[0], Bh[1]);
                mma16816(E[2*nb+1], A2h[kc], Bh[2], Bh[3]);
            }
        }

        {
            const int n = p >> 7, l = p & 127;
            float* dst = xg + ((size_t)((l*3+g)*NB + n))*4096;
            const int r0 = rb*16 + (lane >> 2);
            const int cb = (lane & 3) * 2;
            #pragma unroll
            for (int nb = 0; nb < 4; nb++){
                #pragma unroll
                for (int hf = 0; hf < 2; hf++){
                    int t = 2*nb + hf;
                    int b = nb*16 + hf*8 + cb;
                    float* q = dst + r0*64 + b;
                    *(float2*)q          = make_float2(E[t][0], E[t][1]);
                    *(float2*)(q + 8*64) = make_float2(E[t][2], E[t][3]);
                }
            }
        }
    }
}

// ===================== Phase 2 (Wu2 fragments hoisted to registers) =====================
#define S2_W2H 18432u
#define S2_EP  46080u
#define S2_XGS 98304u
#define S2_MB  150528u
#define S2_BYTES 150656u
#define EPS 68
#define EPP 2176
#define XGB 6528

__global__ void __launch_bounds__(384,1) __cluster_dims__(2,1,1) phase2_mma(
    const float* __restrict__ Wu1, const float* __restrict__ Wu2,
    const float* __restrict__ xg, float* __restrict__ out)
{
    extern __shared__ char sb[];
    const uint32_t s0 = smem_u32(sb);
    float* smf = (float*)sb;
    const int tid = threadIdx.x, wid = tid >> 5, lane = tid & 31;
    uint32_t rk; asm("mov.u32 %0, %%cluster_ctarank;" : "=r"(rk));
    const int n  = blockIdx.x >> 1;
    const int A0 = (int)rk * 32;
    const int EPf = 11520, XGSf = 24576;

    if (tid < 192){
        const int g = tid >> 6, j = tid & 63;
        float w[64];
        #pragma unroll 4
        for (int b = 0; b < 64; b++) w[b] = Wu2[g*4096 + b*64 + j];
        uint32_t eb = (uint32_t)((g*64 + j) * 72);
        #pragma unroll
        for (int k = 0; k < 32; k++)
            *(uint32_t*)(sb + S2_W2H + (eb + 2*k)*2) = cvt2(w[2*k], w[2*k+1]);
    }
    if (tid < 96){
        const int g = tid >> 5, a = tid & 31;
        float w[64];
        #pragma unroll
        for (int q = 0; q < 16; q++)
            ((float4*)w)[q] = ((const float4*)(Wu1 + (size_t)(g*64 + A0 + a)*64))[q];
        uint32_t eb = (uint32_t)((g*32 + a) * 72);
        #pragma unroll
        for (int k = 0; k < 32; k++)
            *(uint32_t*)(sb + S2_XGS + (eb + 2*k)*2) = cvt2(w[2*k], w[2*k+1]);
    }
    for (int i = tid; i < 4608; i += 384) ((uint32_t*)sb)[i] = 0;
    if (tid == 0)
        asm volatile("mbarrier.init.shared.b64 [%0], %1;" :: "r"(s0 + S2_MB), "r"(768u) : "memory");
    __syncthreads();

    const int g  = wid >> 2;
    const int rb = (wid >> 1) & 1;
    const int jh = wid & 1;
    // Wu1 A-fragments (constant over t)
    uint32_t Ah[4][4];
    #pragma unroll
    for (int kc = 0; kc < 4; kc++)
        ldm4(Ah[kc], fraddr(s0 + S2_XGS + (uint32_t)g*4608u, rb*16, kc*16, lane));
    // Wu2 B-fragments (constant over t) — hoisted out of the step loop
    const uint32_t w2hB = s0 + S2_W2H + (uint32_t)g * 9216u;
    uint32_t Bw[2][4][4];
    #pragma unroll
    for (int c = 0; c < 2; c++)
        #pragma unroll
        for (int nb = 0; nb < 4; nb++)
            ldm4t(Bw[c][nb], fraddr(w2hB, jh*32 + c*16, nb*16, lane));
    __syncthreads();

    float cst[2][4];
    #pragma unroll
    for (int cc = 0; cc < 2; cc++)
        #pragma unroll
        for (int k = 0; k < 4; k++) cst[cc][k] = 0.0f;

    uint32_t pb, pbar;
    asm("mapa.shared::cluster.u32 %0, %1, %2;" : "=r"(pb) : "r"(s0), "r"(rk^1u));
    asm("mapa.shared::cluster.u32 %0, %1, %2;" : "=r"(pbar) : "r"(s0 + S2_MB), "r"(rk^1u));

    #pragma unroll
    for (int k = 0; k < 4; k++){
        int idx = tid + 384*k;
        int gx = idx / 512, rem = idx & 511;
        int row = rem >> 4, off = rem & 15;
        cpa16(smf + XGSf + gx*EPP + row*EPS + off*4,
              xg + ((size_t)((0*3 + gx)*NB + n))*4096 + (A0+row)*64 + off*4);
    }
    asm volatile("cp.async.commit_group;");

    asm volatile("barrier.cluster.arrive.aligned;" ::: "memory");
    asm volatile("barrier.cluster.wait.aligned;" ::: "memory");

    int buf = 0, hb = 0;
    for (int t = 0; t < LS; t++){
        const uint32_t hsB = s0 + (uint32_t)hb*9216u;

        // ---- stage1: D = Wu1[g,own16] @ h (jh half) ----
        float D[4][4];
        #pragma unroll
        for (int q = 0; q < 4; q++){ D[q][0]=D[q][1]=D[q][2]=D[q][3]=0.0f; }
        #pragma unroll
        for (int kc = 0; kc < 4; kc++){
            #pragma unroll
            for (int nb = 0; nb < 2; nb++){
                uint32_t Bh[4];
                ldm4t(Bh, fraddr(hsB, kc*16, (jh*2+nb)*16, lane));
                mma16816(D[2*nb],   Ah[kc], Bh[0], Bh[1]);
                mma16816(D[2*nb+1], Ah[kc], Bh[2], Bh[3]);
            }
        }
        uint32_t A2h[2][4];
        #pragma unroll
        for (int c = 0; c < 2; c++){
            A2h[c][0] = cvt2(D[2*c][0],   D[2*c][1]);
            A2h[c][1] = cvt2(D[2*c][2],   D[2*c][3]);
            A2h[c][2] = cvt2(D[2*c+1][0], D[2*c+1][1]);
            A2h[c][3] = cvt2(D[2*c+1][2], D[2*c+1][3]);
        }
        // ---- stage2: pure repack->mma (B in registers) ----
        float E[8][4];
        #pragma unroll
        for (int q = 0; q < 8; q++){ E[q][0]=E[q][1]=E[q][2]=E[q][3]=0.0f; }
        #pragma unroll
        for (int c = 0; c < 2; c++){
            #pragma unroll
            for (int nb = 0; nb < 4; nb++){
                mma16816(E[2*nb],   A2h[c], Bw[c][nb][0], Bw[c][nb][1]);
                mma16816(E[2*nb+1], A2h[c], Bw[c][nb][2], Bw[c][nb][3]);
            }
        }
        // ---- store E partial ----
        {
            float* dst = smf + EPf + (jh*3 + g)*EPP;
            const int r0 = rb*16 + (lane >> 2);
            const int cb = (lane & 3) * 2;
            #pragma unroll
            for (int nb = 0; nb < 4; nb++){
                #pragma unroll
                for (int hf = 0; hf < 2; hf++){
                    int q = 2*nb + hf;
                    int b = nb*16 + hf*8 + cb;
                    float* d2 = dst + r0*EPS + b;
                    *(float2*)d2            = make_float2(E[q][0], E[q][1]);
                    *(float2*)(d2 + 8*EPS)  = make_float2(E[q][2], E[q][3]);
                }
            }
        }
        asm volatile("cp.async.wait_group 0;");
        __syncthreads();

        // ---- epilogue: all 384 threads ----
        float hv[2][4];
        const uint32_t hwb = (uint32_t)(hb^1)*9216u;
        #pragma unroll
        for (int cc = 0; cc < 2; cc++){
            int ch = tid + cc*384;
            if (ch < 512){
                int row = ch >> 4, c4 = (ch & 15) * 4;
                int be = row*EPS + c4;
                const float* ep = smf + EPf;
                const float* xb = smf + XGSf + buf*XGB;
                float4 z1 = *(const float4*)(ep + be);
                float4 z2 = *(const float4*)(ep + 3*EPP + be);
                float4 z3 = *(const float4*)(xb + be);
                float4 r1 = *(const float4*)(ep + 1*EPP + be);
                float4 r2 = *(const float4*)(ep + 4*EPP + be);
                float4 r3 = *(const float4*)(xb + 1*EPP + be);
                float4 o1 = *(const float4*)(ep + 2*EPP + be);
                float4 o2 = *(const float4*)(ep + 5*EPP + be);
                float4 o3 = *(const float4*)(xb + 2*EPP + be);
                float zs[4] = {z1.x+z2.x+z3.x, z1.y+z2.y+z3.y, z1.z+z2.z+z3.z, z1.w+z2.w+z3.w};
                float rs[4] = {r1.x+r2.x+r3.x, r1.y+r2.y+r3.y, r1.z+r2.z+r3.z, r1.w+r2.w+r3.w};
                float os[4] = {o1.x+o2.x+o3.x, o1.y+o2.y+o3.y, o1.z+o2.z+o3.z, o1.w+o2.w+o3.w};
                #pragma unroll
                for (int k = 0; k < 4; k++){
                    float z = sigm(zs[k]);
                    float r = sigm(rs[k]);
                    float o = sigm(os[k]);
                    cst[cc][k] = r * (cst[cc][k] + z);
                    hv[cc][k] = o * sigm(cst[cc][k]);
                }
                uint32_t u01 = cvt2(hv[cc][0], hv[cc][1]);
                uint32_t u23 = cvt2(hv[cc][2], hv[cc][3]);
                uint64_t hpk;
                asm("mov.b64 %0, {%1,%2};" : "=l"(hpk) : "r"(u01), "r"(u23));
                const uint32_t ho = (uint32_t)(((A0 + row)*72 + c4) * 2);
                *(uint64_t*)(sb + hwb + ho) = hpk;
                asm volatile("st.shared::cluster.b64 [%0], %1;" :: "r"(pb + hwb + ho), "l"(hpk));
            }
        }
        asm volatile("mbarrier.arrive.release.cluster.shared::cluster.b64 _, [%0];"
                     :: "r"(s0 + S2_MB) : "memory");
        asm volatile("mbarrier.arrive.release.cluster.shared::cluster.b64 _, [%0];"
                     :: "r"(pbar) : "memory");

        // overlap: output STG + next xg prefetch before waiting
        #pragma unroll
        for (int cc = 0; cc < 2; cc++){
            int ch = tid + cc*384;
            if (ch < 512){
                int row = ch >> 4, c4 = (ch & 15) * 4;
                float* od2 = out + ((size_t)(n*LS + t))*4096 + (A0 + row)*64 + c4;
                *(float4*)od2 = make_float4(hv[cc][0],hv[cc][1],hv[cc][2],hv[cc][3]);
                if (t == LS-1){
                    float* hl2 = out + (size_t)NB*LS*4096 + (size_t)n*4096 + (A0 + row)*64 + c4;
                    *(float4*)hl2 = make_float4(hv[cc][0],hv[cc][1],hv[cc][2],hv[cc][3]);
                }
            }
        }
        if (t + 1 < LS){
            #pragma unroll
            for (int k = 0; k < 4; k++){
                int idx = tid + 384*k;
                int gx = idx / 512, rem = idx & 511;
                int row = rem >> 4, off = rem & 15;
                cpa16(smf + XGSf + (buf^1)*XGB + gx*EPP + row*EPS + off*4,
                      xg + ((size_t)(((t+1)*3 + gx)*NB + n))*4096 + (A0+row)*64 + off*4);
            }
        }
        asm volatile("cp.async.commit_group;");

        mbar_waitc(s0 + S2_MB, (uint32_t)(t & 1));
        buf ^= 1; hb ^= 1;
    }

    #pragma unroll
    for (int cc = 0; cc < 2; cc++){
        int ch = tid + cc*384;
        if (ch < 512){
            int row = ch >> 4, c4 = (ch & 15) * 4;
            float* cl = out + (size_t)NB*LS*4096 + (size_t)NB*4096
                            + (size_t)n*4096 + (A0 + row)*64 + c4;
            *(float4*)cl = make_float4(cst[cc][0],cst[cc][1],cst[cc][2],cst[cc][3]);
        }
    }
    asm volatile("barrier.cluster.arrive.aligned;" ::: "memory");
    asm volatile("barrier.cluster.wait.aligned;" ::: "memory");
}

// ---------------------------------------------------------------------------
extern "C" void kernel_launch(void* const* d_in, const int* in_sizes, int n_in,
                              void* d_out, int out_size)
{
    const float* x   = (const float*)d_in[0];
    const float* Ww1 = (const float*)d_in[1];
    const float* Ww2 = (const float*)d_in[2];
    const float* Wu1 = (const float*)d_in[3];
    const float* Wu2 = (const float*)d_in[4];
    float* out = (float*)d_out;

    float* xg = nullptr;
    cudaGetSymbolAddress((void**)&xg, g_xg);

    cudaFuncSetAttribute(phase1_mma, cudaFuncAttributeMaxDynamicSharedMemorySize, (int)P1_BYTES);
    cudaFuncSetAttribute(phase2_mma, cudaFuncAttributeMaxDynamicSharedMemorySize, (int)S2_BYTES);

    phase1_mma<<<148, 384, P1_BYTES>>>(x, Ww1, Ww2, xg);
    phase2_mma<<<2 * NB, 384, S2_BYTES>>>(Wu1, Wu2, xg, out);
}